// round 15
// baseline (speedup 1.0000x reference)
#include <cuda_runtime.h>
#include <cuda_bf16.h>

// ---------------- problem constants ----------------
#define B 64
#define EPG 512
#define E_TOT (B * EPG)        // 32768
#define NODE_DIM 64
#define EDGE_DIM 32
#define HID 128
#define HEADS 8
#define DH 16
#define FEAT_DIM 160           // 2*64 + 32

// GEMM smem strides. A: fp32 words, 40 ≡ 8 (mod 32); float2 frag loads use
// 8B banks: (20g+t) mod 32 bijective -> conflict-free. B: packed bf16x2
// unsigned, stride 136 ≡ 8 (mod 32): (8t+g) bijective -> conflict-free.
#define ASTRIDE 40
#define BSTRIDE 136
// TRIPLE-buffered: 3 stages x (A raw fp32 + B packed hi/lo)
// = (3*128*40 + 3*2*16*136) * 4 = 113664 bytes; 2 CTA/SM = 227328 <= 228KB/SM.
#define ASTAGE (128 * ASTRIDE)
#define BSTAGE (2 * 16 * BSTRIDE)
#define SMEM_GEMM_BYTES ((3 * ASTAGE + 3 * BSTAGE) * 4)

// dense-attention smem strides (words) — bank-verified conflict-free.
#define KSTR 20
#define VSTR 24
#define PSTR 36
#define SMEM_DATTN ((512 * KSTR + 512 * VSTR + 8 * 64 * PSTR) * 4)     // 163840

// pre-split packed-bf16 weight offsets (in k-PAIR units: [k/2][128])
#define P_INW1 0
#define P_INW2 10240
#define P_WQ   18432
#define P_WK   43008
#define P_WV   67584
#define P_WO   92160
#define P_FW1  116736
#define P_FW2  141312
#define P_PWK  165888
#define P_PWV  174080
#define W_PAIRS 182272
#define LAYER_PSTRIDE 8192

// ---------------- scratch (device globals; no allocs allowed) ----------------
__device__ float g_h[E_TOT * HID];
__device__ float g_q[E_TOT * HID];
__device__ float g_k[E_TOT * HID];
__device__ float g_v[E_TOT * HID];
__device__ float g_a[E_TOT * HID];
__device__ float g_t[E_TOT * HID];
__device__ float g_feat[E_TOT * FEAT_DIM];
__device__ unsigned g_mask[B * EPG * 16];   // 512 bits per (graph,row)
__device__ unsigned g_wphi[W_PAIRS];
__device__ unsigned g_wplo[W_PAIRS];
__device__ float g_qpool[HID];
__device__ float g_pool[B * HID];
__device__ float g_pool2[B * HID];

// ---------------- helpers ----------------
__device__ __forceinline__ unsigned f2tf32u(float f) {
    unsigned u;
    asm("cvt.rna.tf32.f32 %0, %1;" : "=r"(u) : "f"(f));
    return u;
}

__device__ __forceinline__ void split_tf32(float x, unsigned& hi, unsigned& lo) {
    hi = f2tf32u(x);
    lo = f2tf32u(x - __uint_as_float(hi));
}

// bf16 truncation split of a k-adjacent float pair (v.x = even k, v.y = odd k):
// hi = packed top-16-bit truncations (low half = even k), lo = packed bf16 of
// the exact residuals.
__device__ __forceinline__ void bf16pair(float2 v, unsigned& hi, unsigned& lo) {
    unsigned u0 = __float_as_uint(v.x), u1 = __float_as_uint(v.y);
    hi = __byte_perm(u0, u1, 0x7632);
    float l0 = v.x - __uint_as_float(u0 & 0xFFFF0000u);
    float l1 = v.y - __uint_as_float(u1 & 0xFFFF0000u);
    asm("cvt.rn.bf16x2.f32 %0, %1, %2;" : "=r"(lo) : "f"(l1), "f"(l0));
}

__device__ __forceinline__ void cp_async16(unsigned smem_addr, const void* gptr) {
    asm volatile("cp.async.cg.shared.global [%0], [%1], 16;\n"
                 :: "r"(smem_addr), "l"(gptr));
}

__device__ __forceinline__ void mma_tf32(float* c,
                                         unsigned a0, unsigned a1, unsigned a2, unsigned a3,
                                         unsigned b0, unsigned b1) {
    asm volatile("mma.sync.aligned.m16n8k8.row.col.f32.tf32.tf32.f32 "
                 "{%0,%1,%2,%3}, {%4,%5,%6,%7}, {%8,%9}, {%0,%1,%2,%3};"
                 : "+f"(c[0]), "+f"(c[1]), "+f"(c[2]), "+f"(c[3])
                 : "r"(a0), "r"(a1), "r"(a2), "r"(a3), "r"(b0), "r"(b1));
}

__device__ __forceinline__ void mma_bf16(float* c, const unsigned* a,
                                         unsigned b0, unsigned b1) {
    asm volatile("mma.sync.aligned.m16n8k16.row.col.f32.bf16.bf16.f32 "
                 "{%0,%1,%2,%3}, {%4,%5,%6,%7}, {%8,%9}, {%0,%1,%2,%3};"
                 : "+f"(c[0]), "+f"(c[1]), "+f"(c[2]), "+f"(c[3])
                 : "r"(a[0]), "r"(a[1]), "r"(a[2]), "r"(a[3]), "r"(b0), "r"(b1));
}

// ---------------- one-shot weight pre-split into packed bf16 hi/lo pairs -------
// Pair p = [kpair][n] within each weight; src elements (2*kpair)*128+n and +128.
__global__ void split_wp_kernel(const float* __restrict__ w0, const float* __restrict__ w1,
                                const float* __restrict__ w2, const float* __restrict__ w3,
                                const float* __restrict__ w4, const float* __restrict__ w5,
                                const float* __restrict__ w6, const float* __restrict__ w7,
                                const float* __restrict__ w8, const float* __restrict__ w9,
                                unsigned* __restrict__ hi, unsigned* __restrict__ lo) {
    int p = blockIdx.x * 256 + threadIdx.x;
    const float* w;
    int q;
    if      (p < P_INW2) { w = w0; q = p; }
    else if (p < P_WQ)   { w = w1; q = p - P_INW2; }
    else if (p < P_WK)   { w = w2; q = p - P_WQ; }
    else if (p < P_WV)   { w = w3; q = p - P_WK; }
    else if (p < P_WO)   { w = w4; q = p - P_WV; }
    else if (p < P_FW1)  { w = w5; q = p - P_WO; }
    else if (p < P_FW2)  { w = w6; q = p - P_FW1; }
    else if (p < P_PWK)  { w = w7; q = p - P_FW2; }
    else if (p < P_PWV)  { w = w8; q = p - P_PWK; }
    else                 { w = w9; q = p - P_PWV; }
    int e0 = (q >> 7) * 256 + (q & 127);
    float2 v = make_float2(w[e0], w[e0 + 128]);
    unsigned h, l;
    bf16pair(v, h, l);
    hi[p] = h;
    lo[p] = l;
}

// ---------------- gather edge features ----------------
__global__ void gather_feat_kernel(const float* __restrict__ x,
                                   const float* __restrict__ ea,
                                   const int* __restrict__ ei,
                                   float* __restrict__ feat) {
    int e = blockIdx.x;
    int c = threadIdx.x;            // 160 threads
    int s = ei[e];
    int d = ei[E_TOT + e];
    float val;
    if (c < 64)       val = x[(size_t)s * NODE_DIM + c];
    else if (c < 128) val = x[(size_t)d * NODE_DIM + (c - 64)];
    else              val = ea[(size_t)e * EDGE_DIM + (c - 128)];
    feat[(size_t)e * FEAT_DIM + c] = val;
}

// ---------------- adjacency bitmask (edges sharing a node) ----------------
__global__ void build_mask_kernel(const int* __restrict__ ei,
                                  unsigned* __restrict__ mask) {
    int b = blockIdx.x;
    __shared__ int ss[EPG];
    __shared__ int dd[EPG];
    for (int i = threadIdx.x; i < EPG; i += blockDim.x) {
        ss[i] = ei[b * EPG + i];
        dd[i] = ei[E_TOT + b * EPG + i];
    }
    __syncthreads();
    for (int i = threadIdx.x; i < EPG; i += blockDim.x) {
        int si = ss[i], di = dd[i];
        for (int w = 0; w < 16; w++) {
            unsigned bits = 0;
            #pragma unroll
            for (int jj = 0; jj < 32; jj++) {
                int j = (w << 5) + jj;
                int sj = ss[j], dj = dd[j];
                bool adj = (si == sj) | (si == dj) | (di == sj) | (di == dj) | (i == j);
                bits |= (unsigned)adj << jj;
            }
            mask[((size_t)b * EPG + i) * 16 + w] = bits;
        }
    }
}

// ---------------- 3-term bf16 tensor-core GEMM, optional fused res+LN ----------
// C = Ah*Bh + Ah*Bl + Al*Bh (truncation splits, ~16-17 effective mantissa bits).
// W pre-split+packed in global; A staged raw fp32 via cp.async, split in regs.
// 128x128 tile, BK=32, 256 threads (4m x 2n warps), TRIPLE-buffered pipeline:
// one barrier per stage; loads for stage s+2 issued before computing stage s.
__global__ void __launch_bounds__(256, 2)
gemm_bf16_kernel(const float* __restrict__ A,
                 const unsigned* __restrict__ Whi0, const unsigned* __restrict__ Whi1,
                 const unsigned* __restrict__ Whi2,
                 const unsigned* __restrict__ Wlo0, const unsigned* __restrict__ Wlo1,
                 const unsigned* __restrict__ Wlo2,
                 float* __restrict__ C0, float* __restrict__ C1, float* __restrict__ C2,
                 const float* __restrict__ bias, int K, int relu,
                 const float* __restrict__ ln_g, const float* __restrict__ ln_b,
                 float* __restrict__ res) {
    const unsigned* WH = (blockIdx.y == 0) ? Whi0 : (blockIdx.y == 1 ? Whi1 : Whi2);
    const unsigned* WL = (blockIdx.y == 0) ? Wlo0 : (blockIdx.y == 1 ? Wlo1 : Wlo2);
    float* C           = (blockIdx.y == 0) ? C0   : (blockIdx.y == 1 ? C1   : C2);

    extern __shared__ float sm[];
    float* Abuf[3] = { sm, sm + ASTAGE, sm + 2 * ASTAGE };
    unsigned* Bbase = (unsigned*)(sm + 3 * ASTAGE);
    unsigned* BHbuf[3] = { Bbase, Bbase + BSTAGE, Bbase + 2 * BSTAGE };
    // lo half lives in the second half of each B stage
    unsigned* BLbuf[3] = { Bbase + 16 * BSTRIDE, Bbase + BSTAGE + 16 * BSTRIDE,
                           Bbase + 2 * BSTAGE + 16 * BSTRIDE };

    const int tid = threadIdx.x;
    const int lane = tid & 31;
    const int wid = tid >> 5;
    const int wm = wid >> 1;
    const int wn = wid & 1;
    const int g = lane >> 2;
    const int t = lane & 3;
    const int bm = blockIdx.x * 128;

    float acc[2][8][4];
    #pragma unroll
    for (int i = 0; i < 2; i++)
        #pragma unroll
        for (int j = 0; j < 8; j++)
            #pragma unroll
            for (int r = 0; r < 4; r++) acc[i][j][r] = 0.f;

    const int nst = K >> 5;   // BK = 32 (K = 128 or 160)

    const int a_c4 = tid & 7;
    const unsigned sA[3]  = { (unsigned)__cvta_generic_to_shared(Abuf[0]),
                              (unsigned)__cvta_generic_to_shared(Abuf[1]),
                              (unsigned)__cvta_generic_to_shared(Abuf[2]) };
    const unsigned sBH[3] = { (unsigned)__cvta_generic_to_shared(BHbuf[0]),
                              (unsigned)__cvta_generic_to_shared(BHbuf[1]),
                              (unsigned)__cvta_generic_to_shared(BHbuf[2]) };
    const unsigned sBL[3] = { (unsigned)__cvta_generic_to_shared(BLbuf[0]),
                              (unsigned)__cvta_generic_to_shared(BLbuf[1]),
                              (unsigned)__cvta_generic_to_shared(BLbuf[2]) };

    auto load_stage = [&](int buf, int s) {
        const int k0 = s * 32;
        #pragma unroll
        for (int u = 0; u < 4; u++) {
            int rA = (tid >> 3) + 32 * u;
            cp_async16(sA[buf] + (unsigned)((rA * ASTRIDE + a_c4 * 4) << 2),
                       A + (size_t)(bm + rA) * K + k0 + a_c4 * 4);
        }
        // B: 16 k-pairs x 128 cols packed; 512 uint4 per half -> 2 per thread
        #pragma unroll
        for (int u = 0; u < 2; u++) {
            int id = tid + 256 * u;
            int rp = id >> 5, n4 = id & 31;
            unsigned boff = (unsigned)((rp * BSTRIDE + n4 * 4) << 2);
            const size_t gw = (size_t)(s * 16 + rp) * 128 + n4 * 4;
            cp_async16(sBH[buf] + boff, WH + gw);
            cp_async16(sBL[buf] + boff, WL + gw);
        }
        asm volatile("cp.async.commit_group;\n" ::: "memory");
    };

    load_stage(0, 0);
    if (nst > 1) load_stage(1, 1);

    for (int s = 0; s < nst; s++) {
        if (s + 1 < nst)
            asm volatile("cp.async.wait_group 1;\n" ::: "memory");
        else
            asm volatile("cp.async.wait_group 0;\n" ::: "memory");
        __syncthreads();
        // buffer (s+2)%3 was last read at stage s-1, whose compute every warp
        // finished before passing the barrier above -> safe to reload now.
        if (s + 2 < nst) load_stage((s + 2) % 3, s + 2);

        const float* As = Abuf[s % 3];
        const unsigned* BsH = BHbuf[s % 3];
        const unsigned* BsL = BLbuf[s % 3];

        #pragma unroll
        for (int c = 0; c < 2; c++) {        // two k16 chunks per stage
            const int koff = c * 16;
            unsigned ah[2][4], al[2][4];
            #pragma unroll
            for (int mi = 0; mi < 2; mi++) {
                int m0 = wm * 32 + mi * 16;
                const float* p0 = As + (m0 + g) * ASTRIDE + koff + 2 * t;
                const float* p1 = As + (m0 + g + 8) * ASTRIDE + koff + 2 * t;
                bf16pair(*(const float2*)(p0),     ah[mi][0], al[mi][0]);
                bf16pair(*(const float2*)(p1),     ah[mi][1], al[mi][1]);
                bf16pair(*(const float2*)(p0 + 8), ah[mi][2], al[mi][2]);
                bf16pair(*(const float2*)(p1 + 8), ah[mi][3], al[mi][3]);
            }
            #pragma unroll
            for (int nj = 0; nj < 8; nj++) {
                int n0 = wn * 64 + nj * 8;
                unsigned bh0 = BsH[(c * 8 + t) * BSTRIDE + n0 + g];
                unsigned bh1 = BsH[(c * 8 + t + 4) * BSTRIDE + n0 + g];
                unsigned bl0 = BsL[(c * 8 + t) * BSTRIDE + n0 + g];
                unsigned bl1 = BsL[(c * 8 + t + 4) * BSTRIDE + n0 + g];
                #pragma unroll
                for (int mi = 0; mi < 2; mi++) {
                    float* cc = acc[mi][nj];
                    mma_bf16(cc, ah[mi], bl0, bl1);
                    mma_bf16(cc, al[mi], bh0, bh1);
                    mma_bf16(cc, ah[mi], bh0, bh1);
                }
            }
        }
    }

    if (res != nullptr) {
        // -------- fused residual + LayerNorm epilogue (writes res in place) ------
        __syncthreads();  // all warps done with smem before reuse as reduction buf
        float* sb = sm;
        float rs[2][2], rq[2][2];
        #pragma unroll
        for (int i = 0; i < 2; i++) {
            int row0 = bm + wm * 32 + i * 16 + g;
            float s0 = 0.f, s1 = 0.f, q0 = 0.f, q1 = 0.f;
            #pragma unroll
            for (int j = 0; j < 8; j++) {
                int col = wn * 64 + j * 8 + t * 2;
                float bv0 = bias ? bias[col] : 0.f;
                float bv1 = bias ? bias[col + 1] : 0.f;
                float2 r0 = *(const float2*)&res[(size_t)row0 * 128 + col];
                float2 r1 = *(const float2*)&res[(size_t)(row0 + 8) * 128 + col];
                float v0 = acc[i][j][0] + bv0 + r0.x;
                float v1 = acc[i][j][1] + bv1 + r0.y;
                float v2 = acc[i][j][2] + bv0 + r1.x;
                float v3 = acc[i][j][3] + bv1 + r1.y;
                acc[i][j][0] = v0; acc[i][j][1] = v1;
                acc[i][j][2] = v2; acc[i][j][3] = v3;
                s0 += v0 + v1; q0 += v0 * v0 + v1 * v1;
                s1 += v2 + v3; q1 += v2 * v2 + v3 * v3;
            }
            #pragma unroll
            for (int off = 1; off < 4; off <<= 1) {
                s0 += __shfl_xor_sync(0xFFFFFFFFu, s0, off);
                q0 += __shfl_xor_sync(0xFFFFFFFFu, q0, off);
                s1 += __shfl_xor_sync(0xFFFFFFFFu, s1, off);
                q1 += __shfl_xor_sync(0xFFFFFFFFu, q1, off);
            }
            rs[i][0] = s0; rq[i][0] = q0; rs[i][1] = s1; rq[i][1] = q1;
        }
        if (t == 0) {
            #pragma unroll
            for (int i = 0; i < 2; i++) {
                int rl = wm * 32 + i * 16 + g;
                *(float2*)&sb[(wn * 128 + rl) * 2] = make_float2(rs[i][0], rq[i][0]);
                *(float2*)&sb[(wn * 128 + rl + 8) * 2] = make_float2(rs[i][1], rq[i][1]);
            }
        }
        __syncthreads();
        #pragma unroll
        for (int i = 0; i < 2; i++) {
            int rl = wm * 32 + i * 16 + g;
            #pragma unroll
            for (int rh = 0; rh < 2; rh++) {
                float2 p0 = *(float2*)&sb[(rl + rh * 8) * 2];
                float2 p1 = *(float2*)&sb[(128 + rl + rh * 8) * 2];
                float S = p0.x + p1.x, Q = p0.y + p1.y;
                float mean = S * (1.f / 128.f);
                float var = Q * (1.f / 128.f) - mean * mean;
                float inv = rsqrtf(var + 1e-5f);
                int row = bm + rl + rh * 8;
                #pragma unroll
                for (int j = 0; j < 8; j++) {
                    int col = wn * 64 + j * 8 + t * 2;
                    float v0 = acc[i][j][rh * 2 + 0];
                    float v1 = acc[i][j][rh * 2 + 1];
                    *(float2*)&res[(size_t)row * 128 + col] = make_float2(
                        (v0 - mean) * inv * ln_g[col] + ln_b[col],
                        (v1 - mean) * inv * ln_g[col + 1] + ln_b[col + 1]);
                }
            }
        }
        return;
    }

    // -------- plain epilogue --------
    #pragma unroll
    for (int i = 0; i < 2; i++) {
        int row0 = bm + wm * 32 + i * 16 + g;
        #pragma unroll
        for (int j = 0; j < 8; j++) {
            int col = wn * 64 + j * 8 + t * 2;
            float bv0 = bias ? bias[col] : 0.f;
            float bv1 = bias ? bias[col + 1] : 0.f;
            float v0 = acc[i][j][0] + bv0, v1 = acc[i][j][1] + bv1;
            float v2 = acc[i][j][2] + bv0, v3 = acc[i][j][3] + bv1;
            if (relu) {
                v0 = fmaxf(v0, 0.f); v1 = fmaxf(v1, 0.f);
                v2 = fmaxf(v2, 0.f); v3 = fmaxf(v3, 0.f);
            }
            *(float2*)&C[(size_t)row0 * 128 + col] = make_float2(v0, v1);
            *(float2*)&C[(size_t)(row0 + 8) * 128 + col] = make_float2(v2, v3);
        }
    }
}

// ---------------- dense (S-layer) attention on tensor cores (tf32, unchanged) ----
__global__ void __launch_bounds__(256, 1)
dense_attn_tc_kernel(const float* __restrict__ q, const float* __restrict__ k,
                     const float* __restrict__ v, float* __restrict__ o) {
    extern __shared__ float sm[];
    float* Ks = sm;                      // [512][KSTR]
    float* Vs = Ks + 512 * KSTR;         // [512][VSTR]
    float* Ps = Vs + 512 * VSTR;         // [8][64][PSTR]
    const int b = blockIdx.x >> 3, h = blockIdx.x & 7;
    const int base = b * EPG;
    const int tid = threadIdx.x, lane = tid & 31, wid = tid >> 5;
    const int g = lane >> 2, t = lane & 3;
    float* Pw = Ps + wid * 64 * PSTR;

    for (int i = tid; i < 2048; i += 256) {
        int r = i >> 2, c4 = (i & 3) * 4;
        float4 kv = *(const float4*)(k + (size_t)(base + r) * HID + h * DH + c4);
        float4 vv = *(const float4*)(v + (size_t)(base + r) * HID + h * DH + c4);
        Ks[r * KSTR + c4 + 0] = kv.x; Ks[r * KSTR + c4 + 1] = kv.y;
        Ks[r * KSTR + c4 + 2] = kv.z; Ks[r * KSTR + c4 + 3] = kv.w;
        Vs[r * VSTR + c4 + 0] = vv.x; Vs[r * VSTR + c4 + 1] = vv.y;
        Vs[r * VSTR + c4 + 2] = vv.z; Vs[r * VSTR + c4 + 3] = vv.w;
    }

    unsigned qh[4][2][4], ql[4][2][4];
    #pragma unroll
    for (int mi = 0; mi < 4; mi++) {
        const size_t r0 = (size_t)(base + wid * 64 + mi * 16 + g) * HID + h * DH;
        const size_t r1 = r0 + (size_t)8 * HID;
        #pragma unroll
        for (int ko = 0; ko < 2; ko++) {
            split_tf32(q[r0 + ko * 8 + t],     qh[mi][ko][0], ql[mi][ko][0]);
            split_tf32(q[r1 + ko * 8 + t],     qh[mi][ko][1], ql[mi][ko][1]);
            split_tf32(q[r0 + ko * 8 + t + 4], qh[mi][ko][2], ql[mi][ko][2]);
            split_tf32(q[r1 + ko * 8 + t + 4], qh[mi][ko][3], ql[mi][ko][3]);
        }
    }
    __syncthreads();

    float oacc[4][2][4] = {};
    float lrow[8] = {};

    for (int kc = 0; kc < 16; kc++) {
        const int j0 = kc * 32;
        float sacc[4][4][4] = {};
        #pragma unroll
        for (int ko = 0; ko < 2; ko++) {
            #pragma unroll
            for (int nj = 0; nj < 4; nj++) {
                const float* kp = Ks + (j0 + nj * 8 + g) * KSTR + ko * 8 + t;
                unsigned bh0, bl0, bh1, bl1;
                split_tf32(kp[0], bh0, bl0);
                split_tf32(kp[4], bh1, bl1);
                #pragma unroll
                for (int mi = 0; mi < 4; mi++) {
                    float* cc = sacc[mi][nj];
                    mma_tf32(cc, qh[mi][ko][0], qh[mi][ko][1], qh[mi][ko][2], qh[mi][ko][3], bl0, bl1);
                    mma_tf32(cc, ql[mi][ko][0], ql[mi][ko][1], ql[mi][ko][2], ql[mi][ko][3], bh0, bh1);
                    mma_tf32(cc, qh[mi][ko][0], qh[mi][ko][1], qh[mi][ko][2], qh[mi][ko][3], bh0, bh1);
                }
            }
        }
        #pragma unroll
        for (int mi = 0; mi < 4; mi++) {
            #pragma unroll
            for (int nj = 0; nj < 4; nj++) {
                float p0 = __uint_as_float(f2tf32u(__expf(sacc[mi][nj][0] * 0.25f)));
                float p1 = __uint_as_float(f2tf32u(__expf(sacc[mi][nj][1] * 0.25f)));
                float p2 = __uint_as_float(f2tf32u(__expf(sacc[mi][nj][2] * 0.25f)));
                float p3 = __uint_as_float(f2tf32u(__expf(sacc[mi][nj][3] * 0.25f)));
                lrow[mi * 2 + 0] += p0 + p1;
                lrow[mi * 2 + 1] += p2 + p3;
                *(float2*)(Pw + (mi * 16 + g) * PSTR + nj * 8 + 2 * t) = make_float2(p0, p1);
                *(float2*)(Pw + (mi * 16 + g + 8) * PSTR + nj * 8 + 2 * t) = make_float2(p2, p3);
            }
        }
        __syncwarp();
        #pragma unroll
        for (int k2 = 0; k2 < 4; k2++) {
            unsigned pa[4][4];
            #pragma unroll
            for (int mi = 0; mi < 4; mi++) {
                const float* p0 = Pw + (mi * 16 + g) * PSTR + k2 * 8 + t;
                const float* p1 = Pw + (mi * 16 + g + 8) * PSTR + k2 * 8 + t;
                pa[mi][0] = __float_as_uint(p0[0]);
                pa[mi][1] = __float_as_uint(p1[0]);
                pa[mi][2] = __float_as_uint(p0[4]);
                pa[mi][3] = __float_as_uint(p1[4]);
            }
            #pragma unroll
            for (int nd = 0; nd < 2; nd++) {
                unsigned vb0 = f2tf32u(Vs[(j0 + k2 * 8 + t) * VSTR + nd * 8 + g]);
                unsigned vb1 = f2tf32u(Vs[(j0 + k2 * 8 + t + 4) * VSTR + nd * 8 + g]);
                #pragma unroll
                for (int mi = 0; mi < 4; mi++)
                    mma_tf32(oacc[mi][nd], pa[mi][0], pa[mi][1], pa[mi][2], pa[mi][3], vb0, vb1);
            }
        }
        __syncwarp();
    }

    #pragma unroll
    for (int i = 0; i < 8; i++) {
        lrow[i] += __shfl_xor_sync(0xFFFFFFFFu, lrow[i], 1);
        lrow[i] += __shfl_xor_sync(0xFFFFFFFFu, lrow[i], 2);
    }
    #pragma unroll
    for (int mi = 0; mi < 4; mi++) {
        float inv0 = 1.f / lrow[mi * 2 + 0];
        float inv1 = 1.f / lrow[mi * 2 + 1];
        size_t r0 = (size_t)(base + wid * 64 + mi * 16 + g) * HID + h * DH;
        size_t r1 = r0 + (size_t)8 * HID;
        #pragma unroll
        for (int nd = 0; nd < 2; nd++) {
            *(float2*)(o + r0 + nd * 8 + 2 * t) =
                make_float2(oacc[mi][nd][0] * inv0, oacc[mi][nd][1] * inv0);
            *(float2*)(o + r1 + nd * 8 + 2 * t) =
                make_float2(oacc[mi][nd][2] * inv1, oacc[mi][nd][3] * inv1);
        }
    }
}

// ---------------- small SGEMM (M=64 pool path) ----------------
__global__ void gemm_kernel(const float* __restrict__ A,
                            const float* __restrict__ W,
                            const float* __restrict__ bias,
                            float* __restrict__ C,
                            int K, int relu) {
    __shared__ __align__(16) float As[16][68];
    __shared__ __align__(16) float Ws[16][68];
    int bm = blockIdx.y * 64;
    int bn = blockIdx.x * 64;
    int tid = threadIdx.x;
    int tx = tid & 15;
    int ty = tid >> 4;
    float acc[4][4] = {};

    for (int k0 = 0; k0 < K; k0 += 16) {
        #pragma unroll
        for (int i = tid; i < 1024; i += 256) {
            int r = i >> 4, c = i & 15;
            As[c][r] = A[(size_t)(bm + r) * K + k0 + c];
        }
        #pragma unroll
        for (int i = tid; i < 1024; i += 256) {
            int r = i >> 6, c = i & 63;
            Ws[r][c] = W[(size_t)(k0 + r) * 128 + bn + c];
        }
        __syncthreads();
        #pragma unroll
        for (int kk = 0; kk < 16; kk++) {
            float4 av = *(const float4*)&As[kk][ty * 4];
            float4 wv = *(const float4*)&Ws[kk][tx * 4];
            float a[4] = {av.x, av.y, av.z, av.w};
            float w[4] = {wv.x, wv.y, wv.z, wv.w};
            #pragma unroll
            for (int i = 0; i < 4; i++)
                #pragma unroll
                for (int j = 0; j < 4; j++)
                    acc[i][j] += a[i] * w[j];
        }
        __syncthreads();
    }
    #pragma unroll
    for (int i = 0; i < 4; i++) {
        int row = bm + ty * 4 + i;
        float4 out;
        float* po = (float*)&out;
        #pragma unroll
        for (int j = 0; j < 4; j++) {
            int col = bn + tx * 4 + j;
            float vv = acc[i][j] + (bias ? bias[col] : 0.f);
            if (relu) vv = fmaxf(vv, 0.f);
            po[j] = vv;
        }
        *(float4*)&C[(size_t)row * 128 + bn + tx * 4] = out;
    }
}

// ---------------- masked multi-head attention (M layers) ----------------
__global__ void attn_kernel(const float* __restrict__ q, const float* __restrict__ k,
                            const float* __restrict__ v, float* __restrict__ o,
                            const unsigned* __restrict__ mask) {
    extern __shared__ float4 sm4[];
    float4* kd = sm4;           // 2048 float4
    float4* vd = sm4 + 2048;
    int b = blockIdx.x >> 3;
    int h = blockIdx.x & 7;
    int base = b * EPG;
    const float* kp = k + (size_t)base * HID + h * DH;
    const float* vp = v + (size_t)base * HID + h * DH;
    for (int i = threadIdx.x; i < 2048; i += 256) {
        int r = i >> 2, c = i & 3;
        kd[i] = *(const float4*)(kp + (size_t)r * HID + c * 4);
        vd[i] = *(const float4*)(vp + (size_t)r * HID + c * 4);
    }
    __syncthreads();

    #pragma unroll
    for (int rr = 0; rr < 2; rr++) {
        int i = threadIdx.x + rr * 256;
        const float* qp = q + (size_t)(base + i) * HID + h * DH;
        float4 q0 = *(const float4*)(qp + 0);
        float4 q1 = *(const float4*)(qp + 4);
        float4 q2 = *(const float4*)(qp + 8);
        float4 q3 = *(const float4*)(qp + 12);

        float l = 0.f;
        float4 a0 = {0,0,0,0}, a1 = {0,0,0,0}, a2 = {0,0,0,0}, a3 = {0,0,0,0};

        const unsigned* mp = mask + (size_t)(base + i) * 16;
        #pragma unroll
        for (int w = 0; w < 16; w++) {
            unsigned bits = mp[w];
            while (bits) {
                int jj = __ffs(bits) - 1;
                bits &= bits - 1;
                int j = (w << 5) + jj;
                const float4 k0 = kd[4*j+0], k1 = kd[4*j+1], k2 = kd[4*j+2], k3 = kd[4*j+3];
                float s = q0.x*k0.x + q0.y*k0.y + q0.z*k0.z + q0.w*k0.w
                        + q1.x*k1.x + q1.y*k1.y + q1.z*k1.z + q1.w*k1.w
                        + q2.x*k2.x + q2.y*k2.y + q2.z*k2.z + q2.w*k2.w
                        + q3.x*k3.x + q3.y*k3.y + q3.z*k3.z + q3.w*k3.w;
                float p = __expf(s * 0.25f);   // 1/sqrt(16)
                l += p;
                const float4 v0 = vd[4*j+0], v1 = vd[4*j+1], v2 = vd[4*j+2], v3 = vd[4*j+3];
                a0.x += p*v0.x; a0.y += p*v0.y; a0.z += p*v0.z; a0.w += p*v0.w;
                a1.x += p*v1.x; a1.y += p*v1.y; a1.z += p*v1.z; a1.w += p*v1.w;
                a2.x += p*v2.x; a2.y += p*v2.y; a2.z += p*v2.z; a2.w += p*v2.w;
                a3.x += p*v3.x; a3.y += p*v3.y; a3.z += p*v3.z; a3.w += p*v3.w;
            }
        }

        float inv = 1.f / l;
        float* op = o + (size_t)(base + i) * HID + h * DH;
        *(float4*)(op + 0)  = make_float4(a0.x*inv, a0.y*inv, a0.z*inv, a0.w*inv);
        *(float4*)(op + 4)  = make_float4(a1.x*inv, a1.y*inv, a1.z*inv, a1.w*inv);
        *(float4*)(op + 8)  = make_float4(a2.x*inv, a2.y*inv, a2.z*inv, a2.w*inv);
        *(float4*)(op + 12) = make_float4(a3.x*inv, a3.y*inv, a3.z*inv, a3.w*inv);
    }
}

// ---------------- pooling: qpool = seed @ p_Wq ----------------
__global__ void qpool_kernel(const float* __restrict__ seed, const float* __restrict__ Wq,
                             float* __restrict__ qpool) {
    int c = threadIdx.x;   // 128
    float s = 0.f;
    for (int kk = 0; kk < HID; kk++) s += seed[kk] * Wq[(size_t)kk * HID + c];
    qpool[c] = s;
}

// ---------------- PMA attention: 1 query per graph, full mask ----------------
__global__ void pool_attn_kernel(const float* __restrict__ qpool, const float* __restrict__ k,
                                 const float* __restrict__ v, float* __restrict__ pool) {
    int b = blockIdx.x;
    int w = threadIdx.x >> 5;     // head
    int lane = threadIdx.x & 31;
    float qr[DH];
    #pragma unroll
    for (int d = 0; d < DH; d++) qr[d] = qpool[w * DH + d];

    float s[16];
    float mloc = -1e30f;
    #pragma unroll
    for (int t = 0; t < 16; t++) {
        int j = lane + t * 32;
        const float* kp = k + (size_t)(b * EPG + j) * HID + w * DH;
        float acc = 0.f;
        #pragma unroll
        for (int d = 0; d < DH; d++) acc += qr[d] * kp[d];
        s[t] = acc * 0.25f;
        mloc = fmaxf(mloc, s[t]);
    }
    #pragma unroll
    for (int off = 16; off > 0; off >>= 1)
        mloc = fmaxf(mloc, __shfl_xor_sync(0xFFFFFFFFu, mloc, off));

    float l = 0.f;
    float acc[DH];
    #pragma unroll
    for (int d = 0; d < DH; d++) acc[d] = 0.f;
    #pragma unroll
    for (int t = 0; t < 16; t++) {
        int j = lane + t * 32;
        float p = __expf(s[t] - mloc);
        l += p;
        const float* vp = v + (size_t)(b * EPG + j) * HID + w * DH;
        #pragma unroll
        for (int d = 0; d < DH; d++) acc[d] += p * vp[d];
    }
    #pragma unroll
    for (int off = 16; off > 0; off >>= 1) {
        l += __shfl_xor_sync(0xFFFFFFFFu, l, off);
        #pragma unroll
        for (int d = 0; d < DH; d++)
            acc[d] += __shfl_xor_sync(0xFFFFFFFFu, acc[d], off);
    }
    if (lane == 0) {
        float inv = 1.f / l;
        #pragma unroll
        for (int d = 0; d < DH; d++)
            pool[(size_t)b * HID + w * DH + d] = acc[d] * inv;
    }
}

// ---------------- final: out[b] = o1[b] . out_W2 + out_b2 ----------------
__global__ void final_kernel(const float* __restrict__ o1, const float* __restrict__ W2,
                             const float* __restrict__ b2, float* __restrict__ out) {
    int b = blockIdx.x;
    int lane = threadIdx.x;
    float s = 0.f;
    #pragma unroll
    for (int i = 0; i < 4; i++) {
        int c = lane + 32 * i;
        s += o1[(size_t)b * HID + c] * W2[c];
    }
    #pragma unroll
    for (int off = 16; off > 0; off >>= 1)
        s += __shfl_xor_sync(0xFFFFFFFFu, s, off);
    if (lane == 0) out[b] = s + b2[0];
}

// ---------------- host launch ----------------
extern "C" void kernel_launch(void* const* d_in, const int* in_sizes, int n_in,
                              void* d_out, int out_size) {
    const float* x       = (const float*)d_in[0];
    const float* ea      = (const float*)d_in[1];
    const float* in_W1   = (const float*)d_in[2];
    const float* in_b1   = (const float*)d_in[3];
    const float* in_W2   = (const float*)d_in[4];
    const float* in_b2   = (const float*)d_in[5];
    const float* Wq      = (const float*)d_in[6];
    const float* Wk      = (const float*)d_in[7];
    const float* Wv      = (const float*)d_in[8];
    const float* Wo      = (const float*)d_in[9];
    const float* ln1_g   = (const float*)d_in[10];
    const float* ln1_b   = (const float*)d_in[11];
    const float* ln2_g   = (const float*)d_in[12];
    const float* ln2_b   = (const float*)d_in[13];
    const float* f_W1    = (const float*)d_in[14];
    const float* f_b1    = (const float*)d_in[15];
    const float* f_W2    = (const float*)d_in[16];
    const float* f_b2    = (const float*)d_in[17];
    const float* seed    = (const float*)d_in[18];
    const float* p_Wq    = (const float*)d_in[19];
    const float* p_Wk    = (const float*)d_in[20];
    const float* p_Wv    = (const float*)d_in[21];
    const float* p_Wo    = (const float*)d_in[22];
    const float* out_W1  = (const float*)d_in[23];
    const float* out_b1  = (const float*)d_in[24];
    const float* out_W2  = (const float*)d_in[25];
    const float* out_b2  = (const float*)d_in[26];
    const int*   ei      = (const int*)d_in[27];

    float *p_h, *p_q, *p_k, *p_v, *p_a, *p_t, *p_feat, *p_qpool, *p_pool, *p_pool2;
    unsigned *p_wphi, *p_wplo;
    unsigned* p_mask;
    cudaGetSymbolAddress((void**)&p_h, g_h);
    cudaGetSymbolAddress((void**)&p_q, g_q);
    cudaGetSymbolAddress((void**)&p_k, g_k);
    cudaGetSymbolAddress((void**)&p_v, g_v);
    cudaGetSymbolAddress((void**)&p_a, g_a);
    cudaGetSymbolAddress((void**)&p_t, g_t);
    cudaGetSymbolAddress((void**)&p_feat, g_feat);
    cudaGetSymbolAddress((void**)&p_mask, g_mask);
    cudaGetSymbolAddress((void**)&p_wphi, g_wphi);
    cudaGetSymbolAddress((void**)&p_wplo, g_wplo);
    cudaGetSymbolAddress((void**)&p_qpool, g_qpool);
    cudaGetSymbolAddress((void**)&p_pool, g_pool);
    cudaGetSymbolAddress((void**)&p_pool2, g_pool2);

    cudaFuncSetAttribute(attn_kernel, cudaFuncAttributeMaxDynamicSharedMemorySize, 65536);
    cudaFuncSetAttribute(gemm_bf16_kernel, cudaFuncAttributeMaxDynamicSharedMemorySize,
                         SMEM_GEMM_BYTES);
    cudaFuncSetAttribute(dense_attn_tc_kernel, cudaFuncAttributeMaxDynamicSharedMemorySize,
                         SMEM_DATTN);

    const dim3 g1(E_TOT / 128, 1);
    const dim3 g2(E_TOT / 128, 2);
    const dim3 g3(E_TOT / 128, 3);
    dim3 gSmall(2, 1);

    // weight pre-split + inputs
    split_wp_kernel<<<W_PAIRS / 256, 256>>>(in_W1, in_W2, Wq, Wk, Wv, Wo,
                                            f_W1, f_W2, p_Wk, p_Wv, p_wphi, p_wplo);
    gather_feat_kernel<<<E_TOT, FEAT_DIM>>>(x, ea, ei, p_feat);
    build_mask_kernel<<<B, 256>>>(ei, p_mask);

    #define GEMM1(Ap, OFF, Cp, bias, K, relu) \
        gemm_bf16_kernel<<<g1, 256, SMEM_GEMM_BYTES>>>(Ap, \
            p_wphi + (OFF), p_wphi + (OFF), p_wphi + (OFF), \
            p_wplo + (OFF), p_wplo + (OFF), p_wplo + (OFF), \
            Cp, Cp, Cp, bias, K, relu, nullptr, nullptr, nullptr)

    #define GEMM1_LN(Ap, OFF, bias, lng, lnb, resp) \
        gemm_bf16_kernel<<<g1, 256, SMEM_GEMM_BYTES>>>(Ap, \
            p_wphi + (OFF), p_wphi + (OFF), p_wphi + (OFF), \
            p_wplo + (OFF), p_wplo + (OFF), p_wplo + (OFF), \
            nullptr, nullptr, nullptr, bias, HID, 0, lng, lnb, resp)

    // input MLP
    GEMM1(p_feat, P_INW1, p_t, in_b1, FEAT_DIM, 1);
    GEMM1(p_t, P_INW2, p_h, in_b2, HID, 0);

    // transformer layers: M, M, S
    for (int L = 0; L < 3; L++) {
        const size_t wo = (size_t)L * LAYER_PSTRIDE;
        gemm_bf16_kernel<<<g3, 256, SMEM_GEMM_BYTES>>>(p_h,
            p_wphi + P_WQ + wo, p_wphi + P_WK + wo, p_wphi + P_WV + wo,
            p_wplo + P_WQ + wo, p_wplo + P_WK + wo, p_wplo + P_WV + wo,
            p_q, p_k, p_v, nullptr, HID, 0, nullptr, nullptr, nullptr);
        if (L < 2)
            attn_kernel<<<B * HEADS, 256, 65536>>>(p_q, p_k, p_v, p_a, p_mask);
        else
            dense_attn_tc_kernel<<<B * HEADS, 256, SMEM_DATTN>>>(p_q, p_k, p_v, p_a);
        // h = LN(h + a@Wo) fused
        GEMM1_LN(p_a, P_WO + wo, nullptr, ln1_g + L * HID, ln1_b + L * HID, p_h);
        // t = relu(h@W1 + b1)
        GEMM1(p_h, P_FW1 + wo, p_t, f_b1 + L * HID, HID, 1);
        // h = LN(h + t@W2 + b2) fused
        GEMM1_LN(p_t, P_FW2 + wo, f_b2 + L * HID, ln2_g + L * HID, ln2_b + L * HID, p_h);
    }

    // PMA pooling (fused K/V projection)
    gemm_bf16_kernel<<<g2, 256, SMEM_GEMM_BYTES>>>(p_h,
        p_wphi + P_PWK, p_wphi + P_PWV, p_wphi + P_PWV,
        p_wplo + P_PWK, p_wplo + P_PWV, p_wplo + P_PWV,
        p_k, p_v, p_v, nullptr, HID, 0, nullptr, nullptr, nullptr);
    qpool_kernel<<<1, HID>>>(seed, p_Wq, p_qpool);
    pool_attn_kernel<<<B, 256>>>(p_qpool, p_k, p_v, p_pool);
    gemm_kernel<<<gSmall, 256>>>(p_pool, p_Wo, nullptr, p_pool2, HID, 0);

    // output MLP
    gemm_kernel<<<gSmall, 256>>>(p_pool2, out_W1, out_b1, p_pool, HID, 1);
    final_kernel<<<B, 32>>>(p_pool, out_W2, out_b2, (float*)d_out);
    #undef GEMM1
    #undef GEMM1_LN
}

// round 16
// speedup vs baseline: 1.0262x; 1.0262x over previous
#include <cuda_runtime.h>
#include <cuda_bf16.h>

// ---------------- problem constants ----------------
#define B 64
#define EPG 512
#define E_TOT (B * EPG)        // 32768
#define NODE_DIM 64
#define EDGE_DIM 32
#define HID 128
#define HEADS 8
#define DH 16
#define FEAT_DIM 160           // 2*64 + 32

// GEMM smem strides. A: fp32 words, 40 ≡ 8 (mod 32); float2 frag loads use
// 8B banks: (20g+t) mod 32 bijective -> conflict-free. B: packed bf16x2
// unsigned, stride 136 ≡ 8 (mod 32): (8t+g) bijective -> conflict-free.
#define ASTRIDE 40
#define BSTRIDE 136
// DOUBLE-buffered (R14 proven): A raw fp32 + B packed hi/lo = 75776 bytes.
#define SMEM_GEMM_BYTES ((2 * 128 * ASTRIDE + 4 * 16 * BSTRIDE) * 4)

// dense-attention smem strides (words). KSTR=40: float2 pair loads at
// 8B-bank (20g+t) mod 32 bijective -> conflict-free (same proof as GEMM A).
#define KSTR 40
#define VSTR 24
#define PSTR 36
#define SMEM_DATTN ((512 * KSTR + 512 * VSTR + 8 * 64 * PSTR) * 4)     // 204800

// pre-split packed-bf16 weight offsets (in k-PAIR units: [k/2][128])
#define P_INW1 0
#define P_INW2 10240
#define P_WQ   18432
#define P_WK   43008
#define P_WV   67584
#define P_WO   92160
#define P_FW1  116736
#define P_FW2  141312
#define P_PWK  165888
#define P_PWV  174080
#define W_PAIRS 182272
#define LAYER_PSTRIDE 8192

// ---------------- scratch (device globals; no allocs allowed) ----------------
__device__ float g_h[E_TOT * HID];
__device__ float g_q[E_TOT * HID];
__device__ float g_k[E_TOT * HID];
__device__ float g_v[E_TOT * HID];
__device__ float g_a[E_TOT * HID];
__device__ float g_t[E_TOT * HID];
__device__ float g_feat[E_TOT * FEAT_DIM];
__device__ unsigned g_mask[B * EPG * 16];   // 512 bits per (graph,row)
__device__ unsigned g_wphi[W_PAIRS];
__device__ unsigned g_wplo[W_PAIRS];
__device__ float g_qpool[HID];
__device__ float g_pool[B * HID];
__device__ float g_pool2[B * HID];

// ---------------- helpers ----------------
__device__ __forceinline__ unsigned f2tf32u(float f) {
    unsigned u;
    asm("cvt.rna.tf32.f32 %0, %1;" : "=r"(u) : "f"(f));
    return u;
}

// bf16 truncation split of a k-adjacent float pair (v.x = even k, v.y = odd k):
// hi = packed top-16-bit truncations (low half = even k), lo = packed bf16 of
// the exact residuals.
__device__ __forceinline__ void bf16pair(float2 v, unsigned& hi, unsigned& lo) {
    unsigned u0 = __float_as_uint(v.x), u1 = __float_as_uint(v.y);
    hi = __byte_perm(u0, u1, 0x7632);
    float l0 = v.x - __uint_as_float(u0 & 0xFFFF0000u);
    float l1 = v.y - __uint_as_float(u1 & 0xFFFF0000u);
    asm("cvt.rn.bf16x2.f32 %0, %1, %2;" : "=r"(lo) : "f"(l1), "f"(l0));
}

__device__ __forceinline__ void cp_async16(unsigned smem_addr, const void* gptr) {
    asm volatile("cp.async.cg.shared.global [%0], [%1], 16;\n"
                 :: "r"(smem_addr), "l"(gptr));
}

__device__ __forceinline__ void mma_tf32(float* c,
                                         unsigned a0, unsigned a1, unsigned a2, unsigned a3,
                                         unsigned b0, unsigned b1) {
    asm volatile("mma.sync.aligned.m16n8k8.row.col.f32.tf32.tf32.f32 "
                 "{%0,%1,%2,%3}, {%4,%5,%6,%7}, {%8,%9}, {%0,%1,%2,%3};"
                 : "+f"(c[0]), "+f"(c[1]), "+f"(c[2]), "+f"(c[3])
                 : "r"(a0), "r"(a1), "r"(a2), "r"(a3), "r"(b0), "r"(b1));
}

__device__ __forceinline__ void mma_bf16(float* c, const unsigned* a,
                                         unsigned b0, unsigned b1) {
    asm volatile("mma.sync.aligned.m16n8k16.row.col.f32.bf16.bf16.f32 "
                 "{%0,%1,%2,%3}, {%4,%5,%6,%7}, {%8,%9}, {%0,%1,%2,%3};"
                 : "+f"(c[0]), "+f"(c[1]), "+f"(c[2]), "+f"(c[3])
                 : "r"(a[0]), "r"(a[1]), "r"(a[2]), "r"(a[3]), "r"(b0), "r"(b1));
}

// ---------------- one-shot weight pre-split into packed bf16 hi/lo pairs -------
__global__ void split_wp_kernel(const float* __restrict__ w0, const float* __restrict__ w1,
                                const float* __restrict__ w2, const float* __restrict__ w3,
                                const float* __restrict__ w4, const float* __restrict__ w5,
                                const float* __restrict__ w6, const float* __restrict__ w7,
                                const float* __restrict__ w8, const float* __restrict__ w9,
                                unsigned* __restrict__ hi, unsigned* __restrict__ lo) {
    int p = blockIdx.x * 256 + threadIdx.x;
    const float* w;
    int q;
    if      (p < P_INW2) { w = w0; q = p; }
    else if (p < P_WQ)   { w = w1; q = p - P_INW2; }
    else if (p < P_WK)   { w = w2; q = p - P_WQ; }
    else if (p < P_WV)   { w = w3; q = p - P_WK; }
    else if (p < P_WO)   { w = w4; q = p - P_WV; }
    else if (p < P_FW1)  { w = w5; q = p - P_WO; }
    else if (p < P_FW2)  { w = w6; q = p - P_FW1; }
    else if (p < P_PWK)  { w = w7; q = p - P_FW2; }
    else if (p < P_PWV)  { w = w8; q = p - P_PWK; }
    else                 { w = w9; q = p - P_PWV; }
    int e0 = (q >> 7) * 256 + (q & 127);
    float2 v = make_float2(w[e0], w[e0 + 128]);
    unsigned h, l;
    bf16pair(v, h, l);
    hi[p] = h;
    lo[p] = l;
}

// ---------------- gather edge features ----------------
__global__ void gather_feat_kernel(const float* __restrict__ x,
                                   const float* __restrict__ ea,
                                   const int* __restrict__ ei,
                                   float* __restrict__ feat) {
    int e = blockIdx.x;
    int c = threadIdx.x;            // 160 threads
    int s = ei[e];
    int d = ei[E_TOT + e];
    float val;
    if (c < 64)       val = x[(size_t)s * NODE_DIM + c];
    else if (c < 128) val = x[(size_t)d * NODE_DIM + (c - 64)];
    else              val = ea[(size_t)e * EDGE_DIM + (c - 128)];
    feat[(size_t)e * FEAT_DIM + c] = val;
}

// ---------------- adjacency bitmask (edges sharing a node) ----------------
__global__ void build_mask_kernel(const int* __restrict__ ei,
                                  unsigned* __restrict__ mask) {
    int b = blockIdx.x;
    __shared__ int ss[EPG];
    __shared__ int dd[EPG];
    for (int i = threadIdx.x; i < EPG; i += blockDim.x) {
        ss[i] = ei[b * EPG + i];
        dd[i] = ei[E_TOT + b * EPG + i];
    }
    __syncthreads();
    for (int i = threadIdx.x; i < EPG; i += blockDim.x) {
        int si = ss[i], di = dd[i];
        for (int w = 0; w < 16; w++) {
            unsigned bits = 0;
            #pragma unroll
            for (int jj = 0; jj < 32; jj++) {
                int j = (w << 5) + jj;
                int sj = ss[j], dj = dd[j];
                bool adj = (si == sj) | (si == dj) | (di == sj) | (di == dj) | (i == j);
                bits |= (unsigned)adj << jj;
            }
            mask[((size_t)b * EPG + i) * 16 + w] = bits;
        }
    }
}

// ---------------- 3-term bf16 tensor-core GEMM (R14 proven), opt fused res+LN --
__global__ void __launch_bounds__(256, 2)
gemm_bf16_kernel(const float* __restrict__ A,
                 const unsigned* __restrict__ Whi0, const unsigned* __restrict__ Whi1,
                 const unsigned* __restrict__ Whi2,
                 const unsigned* __restrict__ Wlo0, const unsigned* __restrict__ Wlo1,
                 const unsigned* __restrict__ Wlo2,
                 float* __restrict__ C0, float* __restrict__ C1, float* __restrict__ C2,
                 const float* __restrict__ bias, int K, int relu,
                 const float* __restrict__ ln_g, const float* __restrict__ ln_b,
                 float* __restrict__ res) {
    const unsigned* WH = (blockIdx.y == 0) ? Whi0 : (blockIdx.y == 1 ? Whi1 : Whi2);
    const unsigned* WL = (blockIdx.y == 0) ? Wlo0 : (blockIdx.y == 1 ? Wlo1 : Wlo2);
    float* C           = (blockIdx.y == 0) ? C0   : (blockIdx.y == 1 ? C1   : C2);

    extern __shared__ float sm[];
    float* Abuf[2] = { sm, sm + 128 * ASTRIDE };
    unsigned* BHbuf[2] = { (unsigned*)(sm + 2 * 128 * ASTRIDE),
                           (unsigned*)(sm + 2 * 128 * ASTRIDE) + 16 * BSTRIDE };
    unsigned* BLbuf[2] = { (unsigned*)(sm + 2 * 128 * ASTRIDE) + 2 * 16 * BSTRIDE,
                           (unsigned*)(sm + 2 * 128 * ASTRIDE) + 3 * 16 * BSTRIDE };

    const int tid = threadIdx.x;
    const int lane = tid & 31;
    const int wid = tid >> 5;
    const int wm = wid >> 1;
    const int wn = wid & 1;
    const int g = lane >> 2;
    const int t = lane & 3;
    const int bm = blockIdx.x * 128;

    float acc[2][8][4];
    #pragma unroll
    for (int i = 0; i < 2; i++)
        #pragma unroll
        for (int j = 0; j < 8; j++)
            #pragma unroll
            for (int r = 0; r < 4; r++) acc[i][j][r] = 0.f;

    const int nst = K >> 5;   // BK = 32 (K = 128 or 160)

    const int a_c4 = tid & 7;
    const unsigned sA[2]  = { (unsigned)__cvta_generic_to_shared(Abuf[0]),
                              (unsigned)__cvta_generic_to_shared(Abuf[1]) };
    const unsigned sBH[2] = { (unsigned)__cvta_generic_to_shared(BHbuf[0]),
                              (unsigned)__cvta_generic_to_shared(BHbuf[1]) };
    const unsigned sBL[2] = { (unsigned)__cvta_generic_to_shared(BLbuf[0]),
                              (unsigned)__cvta_generic_to_shared(BLbuf[1]) };

    auto load_stage = [&](int buf, int s) {
        const int k0 = s * 32;
        #pragma unroll
        for (int u = 0; u < 4; u++) {
            int rA = (tid >> 3) + 32 * u;
            cp_async16(sA[buf] + (unsigned)((rA * ASTRIDE + a_c4 * 4) << 2),
                       A + (size_t)(bm + rA) * K + k0 + a_c4 * 4);
        }
        #pragma unroll
        for (int u = 0; u < 2; u++) {
            int id = tid + 256 * u;
            int rp = id >> 5, n4 = id & 31;
            unsigned boff = (unsigned)((rp * BSTRIDE + n4 * 4) << 2);
            const size_t gw = (size_t)(s * 16 + rp) * 128 + n4 * 4;
            cp_async16(sBH[buf] + boff, WH + gw);
            cp_async16(sBL[buf] + boff, WL + gw);
        }
        asm volatile("cp.async.commit_group;\n" ::: "memory");
    };

    load_stage(0, 0);
    if (nst > 1) load_stage(1, 1);

    for (int s = 0; s < nst; s++) {
        if (s + 1 < nst)
            asm volatile("cp.async.wait_group 1;\n" ::: "memory");
        else
            asm volatile("cp.async.wait_group 0;\n" ::: "memory");
        __syncthreads();

        const float* As = Abuf[s & 1];
        const unsigned* BsH = BHbuf[s & 1];
        const unsigned* BsL = BLbuf[s & 1];

        #pragma unroll
        for (int c = 0; c < 2; c++) {        // two k16 chunks per stage
            const int koff = c * 16;
            unsigned ah[2][4], al[2][4];
            #pragma unroll
            for (int mi = 0; mi < 2; mi++) {
                int m0 = wm * 32 + mi * 16;
                const float* p0 = As + (m0 + g) * ASTRIDE + koff + 2 * t;
                const float* p1 = As + (m0 + g + 8) * ASTRIDE + koff + 2 * t;
                bf16pair(*(const float2*)(p0),     ah[mi][0], al[mi][0]);
                bf16pair(*(const float2*)(p1),     ah[mi][1], al[mi][1]);
                bf16pair(*(const float2*)(p0 + 8), ah[mi][2], al[mi][2]);
                bf16pair(*(const float2*)(p1 + 8), ah[mi][3], al[mi][3]);
            }
            #pragma unroll
            for (int nj = 0; nj < 8; nj++) {
                int n0 = wn * 64 + nj * 8;
                unsigned bh0 = BsH[(c * 8 + t) * BSTRIDE + n0 + g];
                unsigned bh1 = BsH[(c * 8 + t + 4) * BSTRIDE + n0 + g];
                unsigned bl0 = BsL[(c * 8 + t) * BSTRIDE + n0 + g];
                unsigned bl1 = BsL[(c * 8 + t + 4) * BSTRIDE + n0 + g];
                #pragma unroll
                for (int mi = 0; mi < 2; mi++) {
                    float* cc = acc[mi][nj];
                    mma_bf16(cc, ah[mi], bl0, bl1);
                    mma_bf16(cc, al[mi], bh0, bh1);
                    mma_bf16(cc, ah[mi], bh0, bh1);
                }
            }
        }
        __syncthreads();
        if (s + 2 < nst) load_stage(s & 1, s + 2);
    }

    if (res != nullptr) {
        // -------- fused residual + LayerNorm epilogue (writes res in place) ------
        float* sb = sm;   // safe: all warps passed final __syncthreads() above
        float rs[2][2], rq[2][2];
        #pragma unroll
        for (int i = 0; i < 2; i++) {
            int row0 = bm + wm * 32 + i * 16 + g;
            float s0 = 0.f, s1 = 0.f, q0 = 0.f, q1 = 0.f;
            #pragma unroll
            for (int j = 0; j < 8; j++) {
                int col = wn * 64 + j * 8 + t * 2;
                float bv0 = bias ? bias[col] : 0.f;
                float bv1 = bias ? bias[col + 1] : 0.f;
                float2 r0 = *(const float2*)&res[(size_t)row0 * 128 + col];
                float2 r1 = *(const float2*)&res[(size_t)(row0 + 8) * 128 + col];
                float v0 = acc[i][j][0] + bv0 + r0.x;
                float v1 = acc[i][j][1] + bv1 + r0.y;
                float v2 = acc[i][j][2] + bv0 + r1.x;
                float v3 = acc[i][j][3] + bv1 + r1.y;
                acc[i][j][0] = v0; acc[i][j][1] = v1;
                acc[i][j][2] = v2; acc[i][j][3] = v3;
                s0 += v0 + v1; q0 += v0 * v0 + v1 * v1;
                s1 += v2 + v3; q1 += v2 * v2 + v3 * v3;
            }
            #pragma unroll
            for (int off = 1; off < 4; off <<= 1) {
                s0 += __shfl_xor_sync(0xFFFFFFFFu, s0, off);
                q0 += __shfl_xor_sync(0xFFFFFFFFu, q0, off);
                s1 += __shfl_xor_sync(0xFFFFFFFFu, s1, off);
                q1 += __shfl_xor_sync(0xFFFFFFFFu, q1, off);
            }
            rs[i][0] = s0; rq[i][0] = q0; rs[i][1] = s1; rq[i][1] = q1;
        }
        if (t == 0) {
            #pragma unroll
            for (int i = 0; i < 2; i++) {
                int rl = wm * 32 + i * 16 + g;
                *(float2*)&sb[(wn * 128 + rl) * 2] = make_float2(rs[i][0], rq[i][0]);
                *(float2*)&sb[(wn * 128 + rl + 8) * 2] = make_float2(rs[i][1], rq[i][1]);
            }
        }
        __syncthreads();
        #pragma unroll
        for (int i = 0; i < 2; i++) {
            int rl = wm * 32 + i * 16 + g;
            #pragma unroll
            for (int rh = 0; rh < 2; rh++) {
                float2 p0 = *(float2*)&sb[(rl + rh * 8) * 2];
                float2 p1 = *(float2*)&sb[(128 + rl + rh * 8) * 2];
                float S = p0.x + p1.x, Q = p0.y + p1.y;
                float mean = S * (1.f / 128.f);
                float var = Q * (1.f / 128.f) - mean * mean;
                float inv = rsqrtf(var + 1e-5f);
                int row = bm + rl + rh * 8;
                #pragma unroll
                for (int j = 0; j < 8; j++) {
                    int col = wn * 64 + j * 8 + t * 2;
                    float v0 = acc[i][j][rh * 2 + 0];
                    float v1 = acc[i][j][rh * 2 + 1];
                    *(float2*)&res[(size_t)row * 128 + col] = make_float2(
                        (v0 - mean) * inv * ln_g[col] + ln_b[col],
                        (v1 - mean) * inv * ln_g[col + 1] + ln_b[col + 1]);
                }
            }
        }
        return;
    }

    // -------- plain epilogue --------
    #pragma unroll
    for (int i = 0; i < 2; i++) {
        int row0 = bm + wm * 32 + i * 16 + g;
        #pragma unroll
        for (int j = 0; j < 8; j++) {
            int col = wn * 64 + j * 8 + t * 2;
            float bv0 = bias ? bias[col] : 0.f;
            float bv1 = bias ? bias[col + 1] : 0.f;
            float v0 = acc[i][j][0] + bv0, v1 = acc[i][j][1] + bv1;
            float v2 = acc[i][j][2] + bv0, v3 = acc[i][j][3] + bv1;
            if (relu) {
                v0 = fmaxf(v0, 0.f); v1 = fmaxf(v1, 0.f);
                v2 = fmaxf(v2, 0.f); v3 = fmaxf(v3, 0.f);
            }
            *(float2*)&C[(size_t)row0 * 128 + col] = make_float2(v0, v1);
            *(float2*)&C[(size_t)(row0 + 8) * 128 + col] = make_float2(v2, v3);
        }
    }
}

// ---------------- dense (S-layer) attention: bf16 QK^T + tf32 PV ----------------
// QK^T = 3-term bf16 k16 (DH=16 -> ONE k16 mma per product, half the MMAs of
// the tf32 version). PV = single tf32 (unchanged). KSTR=40 keeps the float2
// pair loads conflict-free.
__global__ void __launch_bounds__(256, 1)
dense_attn_tc_kernel(const float* __restrict__ q, const float* __restrict__ k,
                     const float* __restrict__ v, float* __restrict__ o) {
    extern __shared__ float sm[];
    float* Ks = sm;                      // [512][KSTR]
    float* Vs = Ks + 512 * KSTR;         // [512][VSTR]
    float* Ps = Vs + 512 * VSTR;         // [8][64][PSTR]
    const int b = blockIdx.x >> 3, h = blockIdx.x & 7;
    const int base = b * EPG;
    const int tid = threadIdx.x, lane = tid & 31, wid = tid >> 5;
    const int g = lane >> 2, t = lane & 3;
    float* Pw = Ps + wid * 64 * PSTR;

    for (int i = tid; i < 2048; i += 256) {
        int r = i >> 2, c4 = (i & 3) * 4;
        float4 kv = *(const float4*)(k + (size_t)(base + r) * HID + h * DH + c4);
        float4 vv = *(const float4*)(v + (size_t)(base + r) * HID + h * DH + c4);
        Ks[r * KSTR + c4 + 0] = kv.x; Ks[r * KSTR + c4 + 1] = kv.y;
        Ks[r * KSTR + c4 + 2] = kv.z; Ks[r * KSTR + c4 + 3] = kv.w;
        Vs[r * VSTR + c4 + 0] = vv.x; Vs[r * VSTR + c4 + 1] = vv.y;
        Vs[r * VSTR + c4 + 2] = vv.z; Vs[r * VSTR + c4 + 3] = vv.w;
    }

    // Q fragments: bf16 k16 a-frag. a0=(row g, d=2t,2t+1) a1=(row g+8, same)
    // a2=(row g, d=2t+8,2t+9) a3=(row g+8, same). DH=16 -> single k16 chunk.
    unsigned qh[4][4], ql[4][4];
    #pragma unroll
    for (int mi = 0; mi < 4; mi++) {
        const size_t r0 = (size_t)(base + wid * 64 + mi * 16 + g) * HID + h * DH;
        const size_t r1 = r0 + (size_t)8 * HID;
        bf16pair(*(const float2*)(q + r0 + 2 * t),     qh[mi][0], ql[mi][0]);
        bf16pair(*(const float2*)(q + r1 + 2 * t),     qh[mi][1], ql[mi][1]);
        bf16pair(*(const float2*)(q + r0 + 2 * t + 8), qh[mi][2], ql[mi][2]);
        bf16pair(*(const float2*)(q + r1 + 2 * t + 8), qh[mi][3], ql[mi][3]);
    }
    __syncthreads();

    float oacc[4][2][4] = {};
    float lrow[8] = {};

    for (int kc = 0; kc < 16; kc++) {
        const int j0 = kc * 32;
        float sacc[4][4][4] = {};
        // S = Q @ K^T: 3-term bf16, one k16 mma per term.
        // b0 = K[n][d=2t,2t+1], b1 = K[n][d=2t+8,2t+9] (pairs packed).
        #pragma unroll
        for (int nj = 0; nj < 4; nj++) {
            const float* kp = Ks + (j0 + nj * 8 + g) * KSTR;
            unsigned bh0, bl0, bh1, bl1;
            bf16pair(*(const float2*)(kp + 2 * t),     bh0, bl0);
            bf16pair(*(const float2*)(kp + 2 * t + 8), bh1, bl1);
            #pragma unroll
            for (int mi = 0; mi < 4; mi++) {
                float* cc = sacc[mi][nj];
                mma_bf16(cc, qh[mi], bl0, bl1);
                mma_bf16(cc, ql[mi], bh0, bh1);
                mma_bf16(cc, qh[mi], bh0, bh1);
            }
        }
        // exp, accumulate l from the truncated p used in the numerator.
        #pragma unroll
        for (int mi = 0; mi < 4; mi++) {
            #pragma unroll
            for (int nj = 0; nj < 4; nj++) {
                float p0 = __uint_as_float(f2tf32u(__expf(sacc[mi][nj][0] * 0.25f)));
                float p1 = __uint_as_float(f2tf32u(__expf(sacc[mi][nj][1] * 0.25f)));
                float p2 = __uint_as_float(f2tf32u(__expf(sacc[mi][nj][2] * 0.25f)));
                float p3 = __uint_as_float(f2tf32u(__expf(sacc[mi][nj][3] * 0.25f)));
                lrow[mi * 2 + 0] += p0 + p1;
                lrow[mi * 2 + 1] += p2 + p3;
                *(float2*)(Pw + (mi * 16 + g) * PSTR + nj * 8 + 2 * t) = make_float2(p0, p1);
                *(float2*)(Pw + (mi * 16 + g + 8) * PSTR + nj * 8 + 2 * t) = make_float2(p2, p3);
            }
        }
        __syncwarp();
        // O += P @ V (single tf32 k8 x4).
        #pragma unroll
        for (int k2 = 0; k2 < 4; k2++) {
            unsigned pa[4][4];
            #pragma unroll
            for (int mi = 0; mi < 4; mi++) {
                const float* p0 = Pw + (mi * 16 + g) * PSTR + k2 * 8 + t;
                const float* p1 = Pw + (mi * 16 + g + 8) * PSTR + k2 * 8 + t;
                pa[mi][0] = __float_as_uint(p0[0]);
                pa[mi][1] = __float_as_uint(p1[0]);
                pa[mi][2] = __float_as_uint(p0[4]);
                pa[mi][3] = __float_as_uint(p1[4]);
            }
            #pragma unroll
            for (int nd = 0; nd < 2; nd++) {
                unsigned vb0 = f2tf32u(Vs[(j0 + k2 * 8 + t) * VSTR + nd * 8 + g]);
                unsigned vb1 = f2tf32u(Vs[(j0 + k2 * 8 + t + 4) * VSTR + nd * 8 + g]);
                #pragma unroll
                for (int mi = 0; mi < 4; mi++)
                    mma_tf32(oacc[mi][nd], pa[mi][0], pa[mi][1], pa[mi][2], pa[mi][3], vb0, vb1);
            }
        }
        __syncwarp();
    }

    #pragma unroll
    for (int i = 0; i < 8; i++) {
        lrow[i] += __shfl_xor_sync(0xFFFFFFFFu, lrow[i], 1);
        lrow[i] += __shfl_xor_sync(0xFFFFFFFFu, lrow[i], 2);
    }
    #pragma unroll
    for (int mi = 0; mi < 4; mi++) {
        float inv0 = 1.f / lrow[mi * 2 + 0];
        float inv1 = 1.f / lrow[mi * 2 + 1];
        size_t r0 = (size_t)(base + wid * 64 + mi * 16 + g) * HID + h * DH;
        size_t r1 = r0 + (size_t)8 * HID;
        #pragma unroll
        for (int nd = 0; nd < 2; nd++) {
            *(float2*)(o + r0 + nd * 8 + 2 * t) =
                make_float2(oacc[mi][nd][0] * inv0, oacc[mi][nd][1] * inv0);
            *(float2*)(o + r1 + nd * 8 + 2 * t) =
                make_float2(oacc[mi][nd][2] * inv1, oacc[mi][nd][3] * inv1);
        }
    }
}

// ---------------- small SGEMM (M=64 pool path) ----------------
__global__ void gemm_kernel(const float* __restrict__ A,
                            const float* __restrict__ W,
                            const float* __restrict__ bias,
                            float* __restrict__ C,
                            int K, int relu) {
    __shared__ __align__(16) float As[16][68];
    __shared__ __align__(16) float Ws[16][68];
    int bm = blockIdx.y * 64;
    int bn = blockIdx.x * 64;
    int tid = threadIdx.x;
    int tx = tid & 15;
    int ty = tid >> 4;
    float acc[4][4] = {};

    for (int k0 = 0; k0 < K; k0 += 16) {
        #pragma unroll
        for (int i = tid; i < 1024; i += 256) {
            int r = i >> 4, c = i & 15;
            As[c][r] = A[(size_t)(bm + r) * K + k0 + c];
        }
        #pragma unroll
        for (int i = tid; i < 1024; i += 256) {
            int r = i >> 6, c = i & 63;
            Ws[r][c] = W[(size_t)(k0 + r) * 128 + bn + c];
        }
        __syncthreads();
        #pragma unroll
        for (int kk = 0; kk < 16; kk++) {
            float4 av = *(const float4*)&As[kk][ty * 4];
            float4 wv = *(const float4*)&Ws[kk][tx * 4];
            float a[4] = {av.x, av.y, av.z, av.w};
            float w[4] = {wv.x, wv.y, wv.z, wv.w};
            #pragma unroll
            for (int i = 0; i < 4; i++)
                #pragma unroll
                for (int j = 0; j < 4; j++)
                    acc[i][j] += a[i] * w[j];
        }
        __syncthreads();
    }
    #pragma unroll
    for (int i = 0; i < 4; i++) {
        int row = bm + ty * 4 + i;
        float4 out;
        float* po = (float*)&out;
        #pragma unroll
        for (int j = 0; j < 4; j++) {
            int col = bn + tx * 4 + j;
            float vv = acc[i][j] + (bias ? bias[col] : 0.f);
            if (relu) vv = fmaxf(vv, 0.f);
            po[j] = vv;
        }
        *(float4*)&C[(size_t)row * 128 + bn + tx * 4] = out;
    }
}

// ---------------- masked multi-head attention (M layers) ----------------
__global__ void attn_kernel(const float* __restrict__ q, const float* __restrict__ k,
                            const float* __restrict__ v, float* __restrict__ o,
                            const unsigned* __restrict__ mask) {
    extern __shared__ float4 sm4[];
    float4* kd = sm4;           // 2048 float4
    float4* vd = sm4 + 2048;
    int b = blockIdx.x >> 3;
    int h = blockIdx.x & 7;
    int base = b * EPG;
    const float* kp = k + (size_t)base * HID + h * DH;
    const float* vp = v + (size_t)base * HID + h * DH;
    for (int i = threadIdx.x; i < 2048; i += 256) {
        int r = i >> 2, c = i & 3;
        kd[i] = *(const float4*)(kp + (size_t)r * HID + c * 4);
        vd[i] = *(const float4*)(vp + (size_t)r * HID + c * 4);
    }
    __syncthreads();

    #pragma unroll
    for (int rr = 0; rr < 2; rr++) {
        int i = threadIdx.x + rr * 256;
        const float* qp = q + (size_t)(base + i) * HID + h * DH;
        float4 q0 = *(const float4*)(qp + 0);
        float4 q1 = *(const float4*)(qp + 4);
        float4 q2 = *(const float4*)(qp + 8);
        float4 q3 = *(const float4*)(qp + 12);

        float l = 0.f;
        float4 a0 = {0,0,0,0}, a1 = {0,0,0,0}, a2 = {0,0,0,0}, a3 = {0,0,0,0};

        const unsigned* mp = mask + (size_t)(base + i) * 16;
        #pragma unroll
        for (int w = 0; w < 16; w++) {
            unsigned bits = mp[w];
            while (bits) {
                int jj = __ffs(bits) - 1;
                bits &= bits - 1;
                int j = (w << 5) + jj;
                const float4 k0 = kd[4*j+0], k1 = kd[4*j+1], k2 = kd[4*j+2], k3 = kd[4*j+3];
                float s = q0.x*k0.x + q0.y*k0.y + q0.z*k0.z + q0.w*k0.w
                        + q1.x*k1.x + q1.y*k1.y + q1.z*k1.z + q1.w*k1.w
                        + q2.x*k2.x + q2.y*k2.y + q2.z*k2.z + q2.w*k2.w
                        + q3.x*k3.x + q3.y*k3.y + q3.z*k3.z + q3.w*k3.w;
                float p = __expf(s * 0.25f);   // 1/sqrt(16)
                l += p;
                const float4 v0 = vd[4*j+0], v1 = vd[4*j+1], v2 = vd[4*j+2], v3 = vd[4*j+3];
                a0.x += p*v0.x; a0.y += p*v0.y; a0.z += p*v0.z; a0.w += p*v0.w;
                a1.x += p*v1.x; a1.y += p*v1.y; a1.z += p*v1.z; a1.w += p*v1.w;
                a2.x += p*v2.x; a2.y += p*v2.y; a2.z += p*v2.z; a2.w += p*v2.w;
                a3.x += p*v3.x; a3.y += p*v3.y; a3.z += p*v3.z; a3.w += p*v3.w;
            }
        }

        float inv = 1.f / l;
        float* op = o + (size_t)(base + i) * HID + h * DH;
        *(float4*)(op + 0)  = make_float4(a0.x*inv, a0.y*inv, a0.z*inv, a0.w*inv);
        *(float4*)(op + 4)  = make_float4(a1.x*inv, a1.y*inv, a1.z*inv, a1.w*inv);
        *(float4*)(op + 8)  = make_float4(a2.x*inv, a2.y*inv, a2.z*inv, a2.w*inv);
        *(float4*)(op + 12) = make_float4(a3.x*inv, a3.y*inv, a3.z*inv, a3.w*inv);
    }
}

// ---------------- pooling: qpool = seed @ p_Wq ----------------
__global__ void qpool_kernel(const float* __restrict__ seed, const float* __restrict__ Wq,
                             float* __restrict__ qpool) {
    int c = threadIdx.x;   // 128
    float s = 0.f;
    for (int kk = 0; kk < HID; kk++) s += seed[kk] * Wq[(size_t)kk * HID + c];
    qpool[c] = s;
}

// ---------------- PMA attention: 1 query per graph, full mask ----------------
__global__ void pool_attn_kernel(const float* __restrict__ qpool, const float* __restrict__ k,
                                 const float* __restrict__ v, float* __restrict__ pool) {
    int b = blockIdx.x;
    int w = threadIdx.x >> 5;     // head
    int lane = threadIdx.x & 31;
    float qr[DH];
    #pragma unroll
    for (int d = 0; d < DH; d++) qr[d] = qpool[w * DH + d];

    float s[16];
    float mloc = -1e30f;
    #pragma unroll
    for (int t = 0; t < 16; t++) {
        int j = lane + t * 32;
        const float* kp = k + (size_t)(b * EPG + j) * HID + w * DH;
        float acc = 0.f;
        #pragma unroll
        for (int d = 0; d < DH; d++) acc += qr[d] * kp[d];
        s[t] = acc * 0.25f;
        mloc = fmaxf(mloc, s[t]);
    }
    #pragma unroll
    for (int off = 16; off > 0; off >>= 1)
        mloc = fmaxf(mloc, __shfl_xor_sync(0xFFFFFFFFu, mloc, off));

    float l = 0.f;
    float acc[DH];
    #pragma unroll
    for (int d = 0; d < DH; d++) acc[d] = 0.f;
    #pragma unroll
    for (int t = 0; t < 16; t++) {
        int j = lane + t * 32;
        float p = __expf(s[t] - mloc);
        l += p;
        const float* vp = v + (size_t)(b * EPG + j) * HID + w * DH;
        #pragma unroll
        for (int d = 0; d < DH; d++) acc[d] += p * vp[d];
    }
    #pragma unroll
    for (int off = 16; off > 0; off >>= 1) {
        l += __shfl_xor_sync(0xFFFFFFFFu, l, off);
        #pragma unroll
        for (int d = 0; d < DH; d++)
            acc[d] += __shfl_xor_sync(0xFFFFFFFFu, acc[d], off);
    }
    if (lane == 0) {
        float inv = 1.f / l;
        #pragma unroll
        for (int d = 0; d < DH; d++)
            pool[(size_t)b * HID + w * DH + d] = acc[d] * inv;
    }
}

// ---------------- final: out[b] = o1[b] . out_W2 + out_b2 ----------------
__global__ void final_kernel(const float* __restrict__ o1, const float* __restrict__ W2,
                             const float* __restrict__ b2, float* __restrict__ out) {
    int b = blockIdx.x;
    int lane = threadIdx.x;
    float s = 0.f;
    #pragma unroll
    for (int i = 0; i < 4; i++) {
        int c = lane + 32 * i;
        s += o1[(size_t)b * HID + c] * W2[c];
    }
    #pragma unroll
    for (int off = 16; off > 0; off >>= 1)
        s += __shfl_xor_sync(0xFFFFFFFFu, s, off);
    if (lane == 0) out[b] = s + b2[0];
}

// ---------------- host launch ----------------
extern "C" void kernel_launch(void* const* d_in, const int* in_sizes, int n_in,
                              void* d_out, int out_size) {
    const float* x       = (const float*)d_in[0];
    const float* ea      = (const float*)d_in[1];
    const float* in_W1   = (const float*)d_in[2];
    const float* in_b1   = (const float*)d_in[3];
    const float* in_W2   = (const float*)d_in[4];
    const float* in_b2   = (const float*)d_in[5];
    const float* Wq      = (const float*)d_in[6];
    const float* Wk      = (const float*)d_in[7];
    const float* Wv      = (const float*)d_in[8];
    const float* Wo      = (const float*)d_in[9];
    const float* ln1_g   = (const float*)d_in[10];
    const float* ln1_b   = (const float*)d_in[11];
    const float* ln2_g   = (const float*)d_in[12];
    const float* ln2_b   = (const float*)d_in[13];
    const float* f_W1    = (const float*)d_in[14];
    const float* f_b1    = (const float*)d_in[15];
    const float* f_W2    = (const float*)d_in[16];
    const float* f_b2    = (const float*)d_in[17];
    const float* seed    = (const float*)d_in[18];
    const float* p_Wq    = (const float*)d_in[19];
    const float* p_Wk    = (const float*)d_in[20];
    const float* p_Wv    = (const float*)d_in[21];
    const float* p_Wo    = (const float*)d_in[22];
    const float* out_W1  = (const float*)d_in[23];
    const float* out_b1  = (const float*)d_in[24];
    const float* out_W2  = (const float*)d_in[25];
    const float* out_b2  = (const float*)d_in[26];
    const int*   ei      = (const int*)d_in[27];

    float *p_h, *p_q, *p_k, *p_v, *p_a, *p_t, *p_feat, *p_qpool, *p_pool, *p_pool2;
    unsigned *p_wphi, *p_wplo;
    unsigned* p_mask;
    cudaGetSymbolAddress((void**)&p_h, g_h);
    cudaGetSymbolAddress((void**)&p_q, g_q);
    cudaGetSymbolAddress((void**)&p_k, g_k);
    cudaGetSymbolAddress((void**)&p_v, g_v);
    cudaGetSymbolAddress((void**)&p_a, g_a);
    cudaGetSymbolAddress((void**)&p_t, g_t);
    cudaGetSymbolAddress((void**)&p_feat, g_feat);
    cudaGetSymbolAddress((void**)&p_mask, g_mask);
    cudaGetSymbolAddress((void**)&p_wphi, g_wphi);
    cudaGetSymbolAddress((void**)&p_wplo, g_wplo);
    cudaGetSymbolAddress((void**)&p_qpool, g_qpool);
    cudaGetSymbolAddress((void**)&p_pool, g_pool);
    cudaGetSymbolAddress((void**)&p_pool2, g_pool2);

    cudaFuncSetAttribute(attn_kernel, cudaFuncAttributeMaxDynamicSharedMemorySize, 65536);
    cudaFuncSetAttribute(gemm_bf16_kernel, cudaFuncAttributeMaxDynamicSharedMemorySize,
                         SMEM_GEMM_BYTES);
    cudaFuncSetAttribute(dense_attn_tc_kernel, cudaFuncAttributeMaxDynamicSharedMemorySize,
                         SMEM_DATTN);

    const dim3 g1(E_TOT / 128, 1);
    const dim3 g2(E_TOT / 128, 2);
    const dim3 g3(E_TOT / 128, 3);
    dim3 gSmall(2, 1);

    // weight pre-split + inputs
    split_wp_kernel<<<W_PAIRS / 256, 256>>>(in_W1, in_W2, Wq, Wk, Wv, Wo,
                                            f_W1, f_W2, p_Wk, p_Wv, p_wphi, p_wplo);
    gather_feat_kernel<<<E_TOT, FEAT_DIM>>>(x, ea, ei, p_feat);
    build_mask_kernel<<<B, 256>>>(ei, p_mask);

    #define GEMM1(Ap, OFF, Cp, bias, K, relu) \
        gemm_bf16_kernel<<<g1, 256, SMEM_GEMM_BYTES>>>(Ap, \
            p_wphi + (OFF), p_wphi + (OFF), p_wphi + (OFF), \
            p_wplo + (OFF), p_wplo + (OFF), p_wplo + (OFF), \
            Cp, Cp, Cp, bias, K, relu, nullptr, nullptr, nullptr)

    #define GEMM1_LN(Ap, OFF, bias, lng, lnb, resp) \
        gemm_bf16_kernel<<<g1, 256, SMEM_GEMM_BYTES>>>(Ap, \
            p_wphi + (OFF), p_wphi + (OFF), p_wphi + (OFF), \
            p_wplo + (OFF), p_wplo + (OFF), p_wplo + (OFF), \
            nullptr, nullptr, nullptr, bias, HID, 0, lng, lnb, resp)

    // input MLP
    GEMM1(p_feat, P_INW1, p_t, in_b1, FEAT_DIM, 1);
    GEMM1(p_t, P_INW2, p_h, in_b2, HID, 0);

    // transformer layers: M, M, S
    for (int L = 0; L < 3; L++) {
        const size_t wo = (size_t)L * LAYER_PSTRIDE;
        gemm_bf16_kernel<<<g3, 256, SMEM_GEMM_BYTES>>>(p_h,
            p_wphi + P_WQ + wo, p_wphi + P_WK + wo, p_wphi + P_WV + wo,
            p_wplo + P_WQ + wo, p_wplo + P_WK + wo, p_wplo + P_WV + wo,
            p_q, p_k, p_v, nullptr, HID, 0, nullptr, nullptr, nullptr);
        if (L < 2)
            attn_kernel<<<B * HEADS, 256, 65536>>>(p_q, p_k, p_v, p_a, p_mask);
        else
            dense_attn_tc_kernel<<<B * HEADS, 256, SMEM_DATTN>>>(p_q, p_k, p_v, p_a);
        // h = LN(h + a@Wo) fused
        GEMM1_LN(p_a, P_WO + wo, nullptr, ln1_g + L * HID, ln1_b + L * HID, p_h);
        // t = relu(h@W1 + b1)
        GEMM1(p_h, P_FW1 + wo, p_t, f_b1 + L * HID, HID, 1);
        // h = LN(h + t@W2 + b2) fused
        GEMM1_LN(p_t, P_FW2 + wo, f_b2 + L * HID, ln2_g + L * HID, ln2_b + L * HID, p_h);
    }

    // PMA pooling (fused K/V projection)
    gemm_bf16_kernel<<<g2, 256, SMEM_GEMM_BYTES>>>(p_h,
        p_wphi + P_PWK, p_wphi + P_PWV, p_wphi + P_PWV,
        p_wplo + P_PWK, p_wplo + P_PWV, p_wplo + P_PWV,
        p_k, p_v, p_v, nullptr, HID, 0, nullptr, nullptr, nullptr);
    qpool_kernel<<<1, HID>>>(seed, p_Wq, p_qpool);
    pool_attn_kernel<<<B, 256>>>(p_qpool, p_k, p_v, p_pool);
    gemm_kernel<<<gSmall, 256>>>(p_pool, p_Wo, nullptr, p_pool2, HID, 0);

    // output MLP
    gemm_kernel<<<gSmall, 256>>>(p_pool2, out_W1, out_b1, p_pool, HID, 1);
    final_kernel<<<B, 32>>>(p_pool, out_W2, out_b2, (float*)d_out);
    #undef GEMM1
    #undef GEMM1_LN
}

// round 17
// speedup vs baseline: 1.0704x; 1.0431x over previous
#include <cuda_runtime.h>
#include <cuda_bf16.h>

// ---------------- problem constants ----------------
#define B 64
#define EPG 512
#define E_TOT (B * EPG)        // 32768
#define NODE_DIM 64
#define EDGE_DIM 32
#define HID 128
#define HEADS 8
#define DH 16
#define FEAT_DIM 160           // 2*64 + 32

// single-weight GEMM smem strides (R14/R16 proven)
#define ASTRIDE 40
#define BSTRIDE 136
#define SMEM_GEMM_BYTES ((2 * 128 * ASTRIDE + 4 * 16 * BSTRIDE) * 4)   // 75776

// multi-weight GEMM: A packed hi/lo RESIDENT (K=128), B double-buffered.
// AP=68: frag-load 32b bank = (4g+t) mod 32, bijective -> conflict-free.
#define AP 68
#define SMEM_MULTI ((2 * 128 * AP + 4 * 16 * BSTRIDE) * 4)             // 104448

// dense-attention smem strides (words) — bank-verified conflict-free.
#define KSTR 40
#define VSTR 24
#define PSTR 36
#define SMEM_DATTN ((512 * KSTR + 512 * VSTR + 8 * 64 * PSTR) * 4)     // 204800

// pre-split packed-bf16 weight offsets (in k-PAIR units: [k/2][128])
#define P_INW1 0
#define P_INW2 10240
#define P_WQ   18432
#define P_WK   43008
#define P_WV   67584
#define P_WO   92160
#define P_FW1  116736
#define P_FW2  141312
#define P_PWK  165888
#define P_PWV  174080
#define W_PAIRS 182272
#define LAYER_PSTRIDE 8192

// ---------------- scratch (device globals; no allocs allowed) ----------------
__device__ float g_h[E_TOT * HID];
__device__ float g_q[E_TOT * HID];
__device__ float g_k[E_TOT * HID];
__device__ float g_v[E_TOT * HID];
__device__ float g_a[E_TOT * HID];
__device__ float g_t[E_TOT * HID];
__device__ float g_feat[E_TOT * FEAT_DIM];
__device__ unsigned g_mask[B * EPG * 16];   // 512 bits per (graph,row)
__device__ unsigned g_wphi[W_PAIRS];
__device__ unsigned g_wplo[W_PAIRS];

// ---------------- helpers ----------------
__device__ __forceinline__ unsigned f2tf32u(float f) {
    unsigned u;
    asm("cvt.rna.tf32.f32 %0, %1;" : "=r"(u) : "f"(f));
    return u;
}

// bf16 truncation split of a k-adjacent float pair (v.x = even k, v.y = odd k).
__device__ __forceinline__ void bf16pair(float2 v, unsigned& hi, unsigned& lo) {
    unsigned u0 = __float_as_uint(v.x), u1 = __float_as_uint(v.y);
    hi = __byte_perm(u0, u1, 0x7632);
    float l0 = v.x - __uint_as_float(u0 & 0xFFFF0000u);
    float l1 = v.y - __uint_as_float(u1 & 0xFFFF0000u);
    asm("cvt.rn.bf16x2.f32 %0, %1, %2;" : "=r"(lo) : "f"(l1), "f"(l0));
}

__device__ __forceinline__ void cp_async16(unsigned smem_addr, const void* gptr) {
    asm volatile("cp.async.cg.shared.global [%0], [%1], 16;\n"
                 :: "r"(smem_addr), "l"(gptr));
}

__device__ __forceinline__ void mma_tf32(float* c,
                                         unsigned a0, unsigned a1, unsigned a2, unsigned a3,
                                         unsigned b0, unsigned b1) {
    asm volatile("mma.sync.aligned.m16n8k8.row.col.f32.tf32.tf32.f32 "
                 "{%0,%1,%2,%3}, {%4,%5,%6,%7}, {%8,%9}, {%0,%1,%2,%3};"
                 : "+f"(c[0]), "+f"(c[1]), "+f"(c[2]), "+f"(c[3])
                 : "r"(a0), "r"(a1), "r"(a2), "r"(a3), "r"(b0), "r"(b1));
}

__device__ __forceinline__ void mma_bf16(float* c, const unsigned* a,
                                         unsigned b0, unsigned b1) {
    asm volatile("mma.sync.aligned.m16n8k16.row.col.f32.bf16.bf16.f32 "
                 "{%0,%1,%2,%3}, {%4,%5,%6,%7}, {%8,%9}, {%0,%1,%2,%3};"
                 : "+f"(c[0]), "+f"(c[1]), "+f"(c[2]), "+f"(c[3])
                 : "r"(a[0]), "r"(a[1]), "r"(a[2]), "r"(a[3]), "r"(b0), "r"(b1));
}

// ---------------- one-shot weight pre-split into packed bf16 hi/lo pairs -------
__global__ void split_wp_kernel(const float* __restrict__ w0, const float* __restrict__ w1,
                                const float* __restrict__ w2, const float* __restrict__ w3,
                                const float* __restrict__ w4, const float* __restrict__ w5,
                                const float* __restrict__ w6, const float* __restrict__ w7,
                                const float* __restrict__ w8, const float* __restrict__ w9,
                                unsigned* __restrict__ hi, unsigned* __restrict__ lo) {
    int p = blockIdx.x * 256 + threadIdx.x;
    const float* w;
    int q;
    if      (p < P_INW2) { w = w0; q = p; }
    else if (p < P_WQ)   { w = w1; q = p - P_INW2; }
    else if (p < P_WK)   { w = w2; q = p - P_WQ; }
    else if (p < P_WV)   { w = w3; q = p - P_WK; }
    else if (p < P_WO)   { w = w4; q = p - P_WV; }
    else if (p < P_FW1)  { w = w5; q = p - P_WO; }
    else if (p < P_FW2)  { w = w6; q = p - P_FW1; }
    else if (p < P_PWK)  { w = w7; q = p - P_FW2; }
    else if (p < P_PWV)  { w = w8; q = p - P_PWK; }
    else                 { w = w9; q = p - P_PWV; }
    int e0 = (q >> 7) * 256 + (q & 127);
    float2 v = make_float2(w[e0], w[e0 + 128]);
    unsigned h, l;
    bf16pair(v, h, l);
    hi[p] = h;
    lo[p] = l;
}

// ---------------- gather edge features ----------------
__global__ void gather_feat_kernel(const float* __restrict__ x,
                                   const float* __restrict__ ea,
                                   const int* __restrict__ ei,
                                   float* __restrict__ feat) {
    int e = blockIdx.x;
    int c = threadIdx.x;            // 160 threads
    int s = ei[e];
    int d = ei[E_TOT + e];
    float val;
    if (c < 64)       val = x[(size_t)s * NODE_DIM + c];
    else if (c < 128) val = x[(size_t)d * NODE_DIM + (c - 64)];
    else              val = ea[(size_t)e * EDGE_DIM + (c - 128)];
    feat[(size_t)e * FEAT_DIM + c] = val;
}

// ---------------- adjacency bitmask (edges sharing a node) ----------------
__global__ void build_mask_kernel(const int* __restrict__ ei,
                                  unsigned* __restrict__ mask) {
    int b = blockIdx.x;
    __shared__ int ss[EPG];
    __shared__ int dd[EPG];
    for (int i = threadIdx.x; i < EPG; i += blockDim.x) {
        ss[i] = ei[b * EPG + i];
        dd[i] = ei[E_TOT + b * EPG + i];
    }
    __syncthreads();
    for (int i = threadIdx.x; i < EPG; i += blockDim.x) {
        int si = ss[i], di = dd[i];
        for (int w = 0; w < 16; w++) {
            unsigned bits = 0;
            #pragma unroll
            for (int jj = 0; jj < 32; jj++) {
                int j = (w << 5) + jj;
                int sj = ss[j], dj = dd[j];
                bool adj = (si == sj) | (si == dj) | (di == sj) | (di == dj) | (i == j);
                bits |= (unsigned)adj << jj;
            }
            mask[((size_t)b * EPG + i) * 16 + w] = bits;
        }
    }
}

// ---------------- single-weight 3-term bf16 GEMM (R16 proven), opt fused res+LN --
__global__ void __launch_bounds__(256, 2)
gemm_bf16_kernel(const float* __restrict__ A,
                 const unsigned* __restrict__ WH, const unsigned* __restrict__ WL,
                 float* __restrict__ C,
                 const float* __restrict__ bias, int K, int relu,
                 const float* __restrict__ ln_g, const float* __restrict__ ln_b,
                 float* __restrict__ res) {
    extern __shared__ float sm[];
    float* Abuf[2] = { sm, sm + 128 * ASTRIDE };
    unsigned* BHbuf[2] = { (unsigned*)(sm + 2 * 128 * ASTRIDE),
                           (unsigned*)(sm + 2 * 128 * ASTRIDE) + 16 * BSTRIDE };
    unsigned* BLbuf[2] = { (unsigned*)(sm + 2 * 128 * ASTRIDE) + 2 * 16 * BSTRIDE,
                           (unsigned*)(sm + 2 * 128 * ASTRIDE) + 3 * 16 * BSTRIDE };

    const int tid = threadIdx.x;
    const int lane = tid & 31;
    const int wid = tid >> 5;
    const int wm = wid >> 1;
    const int wn = wid & 1;
    const int g = lane >> 2;
    const int t = lane & 3;
    const int bm = blockIdx.x * 128;

    float acc[2][8][4];
    #pragma unroll
    for (int i = 0; i < 2; i++)
        #pragma unroll
        for (int j = 0; j < 8; j++)
            #pragma unroll
            for (int r = 0; r < 4; r++) acc[i][j][r] = 0.f;

    const int nst = K >> 5;

    const int a_c4 = tid & 7;
    const unsigned sA[2]  = { (unsigned)__cvta_generic_to_shared(Abuf[0]),
                              (unsigned)__cvta_generic_to_shared(Abuf[1]) };
    const unsigned sBH[2] = { (unsigned)__cvta_generic_to_shared(BHbuf[0]),
                              (unsigned)__cvta_generic_to_shared(BHbuf[1]) };
    const unsigned sBL[2] = { (unsigned)__cvta_generic_to_shared(BLbuf[0]),
                              (unsigned)__cvta_generic_to_shared(BLbuf[1]) };

    auto load_stage = [&](int buf, int s) {
        const int k0 = s * 32;
        #pragma unroll
        for (int u = 0; u < 4; u++) {
            int rA = (tid >> 3) + 32 * u;
            cp_async16(sA[buf] + (unsigned)((rA * ASTRIDE + a_c4 * 4) << 2),
                       A + (size_t)(bm + rA) * K + k0 + a_c4 * 4);
        }
        #pragma unroll
        for (int u = 0; u < 2; u++) {
            int id = tid + 256 * u;
            int rp = id >> 5, n4 = id & 31;
            unsigned boff = (unsigned)((rp * BSTRIDE + n4 * 4) << 2);
            const size_t gw = (size_t)(s * 16 + rp) * 128 + n4 * 4;
            cp_async16(sBH[buf] + boff, WH + gw);
            cp_async16(sBL[buf] + boff, WL + gw);
        }
        asm volatile("cp.async.commit_group;\n" ::: "memory");
    };

    load_stage(0, 0);
    if (nst > 1) load_stage(1, 1);

    for (int s = 0; s < nst; s++) {
        if (s + 1 < nst)
            asm volatile("cp.async.wait_group 1;\n" ::: "memory");
        else
            asm volatile("cp.async.wait_group 0;\n" ::: "memory");
        __syncthreads();

        const float* As = Abuf[s & 1];
        const unsigned* BsH = BHbuf[s & 1];
        const unsigned* BsL = BLbuf[s & 1];

        #pragma unroll
        for (int c = 0; c < 2; c++) {
            const int koff = c * 16;
            unsigned ah[2][4], al[2][4];
            #pragma unroll
            for (int mi = 0; mi < 2; mi++) {
                int m0 = wm * 32 + mi * 16;
                const float* p0 = As + (m0 + g) * ASTRIDE + koff + 2 * t;
                const float* p1 = As + (m0 + g + 8) * ASTRIDE + koff + 2 * t;
                bf16pair(*(const float2*)(p0),     ah[mi][0], al[mi][0]);
                bf16pair(*(const float2*)(p1),     ah[mi][1], al[mi][1]);
                bf16pair(*(const float2*)(p0 + 8), ah[mi][2], al[mi][2]);
                bf16pair(*(const float2*)(p1 + 8), ah[mi][3], al[mi][3]);
            }
            #pragma unroll
            for (int nj = 0; nj < 8; nj++) {
                int n0 = wn * 64 + nj * 8;
                unsigned bh0 = BsH[(c * 8 + t) * BSTRIDE + n0 + g];
                unsigned bh1 = BsH[(c * 8 + t + 4) * BSTRIDE + n0 + g];
                unsigned bl0 = BsL[(c * 8 + t) * BSTRIDE + n0 + g];
                unsigned bl1 = BsL[(c * 8 + t + 4) * BSTRIDE + n0 + g];
                #pragma unroll
                for (int mi = 0; mi < 2; mi++) {
                    float* cc = acc[mi][nj];
                    mma_bf16(cc, ah[mi], bl0, bl1);
                    mma_bf16(cc, al[mi], bh0, bh1);
                    mma_bf16(cc, ah[mi], bh0, bh1);
                }
            }
        }
        __syncthreads();
        if (s + 2 < nst) load_stage(s & 1, s + 2);
    }

    if (res != nullptr) {
        float* sb = sm;
        float rs[2][2], rq[2][2];
        #pragma unroll
        for (int i = 0; i < 2; i++) {
            int row0 = bm + wm * 32 + i * 16 + g;
            float s0 = 0.f, s1 = 0.f, q0 = 0.f, q1 = 0.f;
            #pragma unroll
            for (int j = 0; j < 8; j++) {
                int col = wn * 64 + j * 8 + t * 2;
                float bv0 = bias ? bias[col] : 0.f;
                float bv1 = bias ? bias[col + 1] : 0.f;
                float2 r0 = *(const float2*)&res[(size_t)row0 * 128 + col];
                float2 r1 = *(const float2*)&res[(size_t)(row0 + 8) * 128 + col];
                float v0 = acc[i][j][0] + bv0 + r0.x;
                float v1 = acc[i][j][1] + bv1 + r0.y;
                float v2 = acc[i][j][2] + bv0 + r1.x;
                float v3 = acc[i][j][3] + bv1 + r1.y;
                acc[i][j][0] = v0; acc[i][j][1] = v1;
                acc[i][j][2] = v2; acc[i][j][3] = v3;
                s0 += v0 + v1; q0 += v0 * v0 + v1 * v1;
                s1 += v2 + v3; q1 += v2 * v2 + v3 * v3;
            }
            #pragma unroll
            for (int off = 1; off < 4; off <<= 1) {
                s0 += __shfl_xor_sync(0xFFFFFFFFu, s0, off);
                q0 += __shfl_xor_sync(0xFFFFFFFFu, q0, off);
                s1 += __shfl_xor_sync(0xFFFFFFFFu, s1, off);
                q1 += __shfl_xor_sync(0xFFFFFFFFu, q1, off);
            }
            rs[i][0] = s0; rq[i][0] = q0; rs[i][1] = s1; rq[i][1] = q1;
        }
        if (t == 0) {
            #pragma unroll
            for (int i = 0; i < 2; i++) {
                int rl = wm * 32 + i * 16 + g;
                *(float2*)&sb[(wn * 128 + rl) * 2] = make_float2(rs[i][0], rq[i][0]);
                *(float2*)&sb[(wn * 128 + rl + 8) * 2] = make_float2(rs[i][1], rq[i][1]);
            }
        }
        __syncthreads();
        #pragma unroll
        for (int i = 0; i < 2; i++) {
            int rl = wm * 32 + i * 16 + g;
            #pragma unroll
            for (int rh = 0; rh < 2; rh++) {
                float2 p0 = *(float2*)&sb[(rl + rh * 8) * 2];
                float2 p1 = *(float2*)&sb[(128 + rl + rh * 8) * 2];
                float S = p0.x + p1.x, Q = p0.y + p1.y;
                float mean = S * (1.f / 128.f);
                float var = Q * (1.f / 128.f) - mean * mean;
                float inv = rsqrtf(var + 1e-5f);
                int row = bm + rl + rh * 8;
                #pragma unroll
                for (int j = 0; j < 8; j++) {
                    int col = wn * 64 + j * 8 + t * 2;
                    float v0 = acc[i][j][rh * 2 + 0];
                    float v1 = acc[i][j][rh * 2 + 1];
                    *(float2*)&res[(size_t)row * 128 + col] = make_float2(
                        (v0 - mean) * inv * ln_g[col] + ln_b[col],
                        (v1 - mean) * inv * ln_g[col + 1] + ln_b[col + 1]);
                }
            }
        }
        return;
    }

    #pragma unroll
    for (int i = 0; i < 2; i++) {
        int row0 = bm + wm * 32 + i * 16 + g;
        #pragma unroll
        for (int j = 0; j < 8; j++) {
            int col = wn * 64 + j * 8 + t * 2;
            float bv0 = bias ? bias[col] : 0.f;
            float bv1 = bias ? bias[col + 1] : 0.f;
            float v0 = acc[i][j][0] + bv0, v1 = acc[i][j][1] + bv1;
            float v2 = acc[i][j][2] + bv0, v3 = acc[i][j][3] + bv1;
            if (relu) {
                v0 = fmaxf(v0, 0.f); v1 = fmaxf(v1, 0.f);
                v2 = fmaxf(v2, 0.f); v3 = fmaxf(v3, 0.f);
            }
            *(float2*)&C[(size_t)row0 * 128 + col] = make_float2(v0, v1);
            *(float2*)&C[(size_t)(row0 + 8) * 128 + col] = make_float2(v2, v3);
        }
    }
}

// ---------------- multi-weight bf16 GEMM (K=128): A packed resident in smem -----
// One 256-block wave computes NW outputs C_w = A @ W_w. A is loaded + split to
// packed bf16 hi/lo ONCE (smem-resident, stride AP: frag bank (4g+t) bijective);
// B streams through the proven double-buffered pipeline across NW*4 stages.
__global__ void __launch_bounds__(256, 2)
gemm_multi_kernel(const float* __restrict__ A,
                  const unsigned* __restrict__ WH0, const unsigned* __restrict__ WH1,
                  const unsigned* __restrict__ WH2,
                  const unsigned* __restrict__ WL0, const unsigned* __restrict__ WL1,
                  const unsigned* __restrict__ WL2,
                  float* __restrict__ C0, float* __restrict__ C1, float* __restrict__ C2,
                  int NW) {
    extern __shared__ float sm[];
    unsigned* AH = (unsigned*)sm;                  // [128][AP]
    unsigned* AL = AH + 128 * AP;
    unsigned* Bb = AL + 128 * AP;
    unsigned* BHbuf[2] = { Bb, Bb + 2 * 16 * BSTRIDE };
    unsigned* BLbuf[2] = { Bb + 16 * BSTRIDE, Bb + 3 * 16 * BSTRIDE };

    const unsigned* WH[3] = { WH0, WH1, WH2 };
    const unsigned* WL[3] = { WL0, WL1, WL2 };
    float* Cs[3] = { C0, C1, C2 };

    const int tid = threadIdx.x;
    const int lane = tid & 31;
    const int wid = tid >> 5;
    const int wm = wid >> 1;
    const int wn = wid & 1;
    const int g = lane >> 2;
    const int t = lane & 3;
    const int bm = blockIdx.x * 128;

    const unsigned sBH[2] = { (unsigned)__cvta_generic_to_shared(BHbuf[0]),
                              (unsigned)__cvta_generic_to_shared(BHbuf[1]) };
    const unsigned sBL[2] = { (unsigned)__cvta_generic_to_shared(BLbuf[0]),
                              (unsigned)__cvta_generic_to_shared(BLbuf[1]) };

    auto load_B = [&](int buf, int gs) {
        const int w = gs >> 2, s = gs & 3;
        #pragma unroll
        for (int u = 0; u < 2; u++) {
            int id = tid + 256 * u;
            int rp = id >> 5, n4 = id & 31;
            unsigned boff = (unsigned)((rp * BSTRIDE + n4 * 4) << 2);
            const size_t gw = (size_t)(s * 16 + rp) * 128 + n4 * 4;
            cp_async16(sBH[buf] + boff, WH[w] + gw);
            cp_async16(sBL[buf] + boff, WL[w] + gw);
        }
        asm volatile("cp.async.commit_group;\n" ::: "memory");
    };

    const int nst = NW * 4;
    load_B(0, 0);
    load_B(1, 1);

    // A load + split (overlaps the in-flight cp.asyncs). 4096 float4 total.
    #pragma unroll
    for (int u = 0; u < 16; u++) {
        int idx = tid + 256 * u;
        int r = idx >> 5, c4 = idx & 31;
        float4 av = *(const float4*)(A + (size_t)(bm + r) * 128 + c4 * 4);
        unsigned h0, l0, h1, l1;
        bf16pair(make_float2(av.x, av.y), h0, l0);
        bf16pair(make_float2(av.z, av.w), h1, l1);
        AH[r * AP + c4 * 2] = h0; AH[r * AP + c4 * 2 + 1] = h1;
        AL[r * AP + c4 * 2] = l0; AL[r * AP + c4 * 2 + 1] = l1;
    }
    __syncthreads();   // A ready for all warps

    float acc[2][8][4];
    #pragma unroll
    for (int i = 0; i < 2; i++)
        #pragma unroll
        for (int j = 0; j < 8; j++)
            #pragma unroll
            for (int r = 0; r < 4; r++) acc[i][j][r] = 0.f;

    for (int gs = 0; gs < nst; gs++) {
        if (gs + 1 < nst)
            asm volatile("cp.async.wait_group 1;\n" ::: "memory");
        else
            asm volatile("cp.async.wait_group 0;\n" ::: "memory");
        __syncthreads();

        const unsigned* BsH = BHbuf[gs & 1];
        const unsigned* BsL = BLbuf[gs & 1];
        const int s = gs & 3;

        #pragma unroll
        for (int c = 0; c < 2; c++) {
            const int kp0 = s * 16 + c * 8;   // kpair base for this chunk
            unsigned ah[2][4], al[2][4];
            #pragma unroll
            for (int mi = 0; mi < 2; mi++) {
                int m0 = wm * 32 + mi * 16;
                int b0 = (m0 + g) * AP + kp0 + t;
                int b1 = (m0 + g + 8) * AP + kp0 + t;
                ah[mi][0] = AH[b0]; ah[mi][1] = AH[b1];
                ah[mi][2] = AH[b0 + 4]; ah[mi][3] = AH[b1 + 4];
                al[mi][0] = AL[b0]; al[mi][1] = AL[b1];
                al[mi][2] = AL[b0 + 4]; al[mi][3] = AL[b1 + 4];
            }
            #pragma unroll
            for (int nj = 0; nj < 8; nj++) {
                int n0 = wn * 64 + nj * 8;
                unsigned bh0 = BsH[(c * 8 + t) * BSTRIDE + n0 + g];
                unsigned bh1 = BsH[(c * 8 + t + 4) * BSTRIDE + n0 + g];
                unsigned bl0 = BsL[(c * 8 + t) * BSTRIDE + n0 + g];
                unsigned bl1 = BsL[(c * 8 + t + 4) * BSTRIDE + n0 + g];
                #pragma unroll
                for (int mi = 0; mi < 2; mi++) {
                    float* cc = acc[mi][nj];
                    mma_bf16(cc, ah[mi], bl0, bl1);
                    mma_bf16(cc, al[mi], bh0, bh1);
                    mma_bf16(cc, ah[mi], bh0, bh1);
                }
            }
        }
        __syncthreads();
        if (gs + 2 < nst) load_B(gs & 1, gs + 2);

        if (s == 3) {
            float* C = Cs[gs >> 2];
            #pragma unroll
            for (int i = 0; i < 2; i++) {
                int row0 = bm + wm * 32 + i * 16 + g;
                #pragma unroll
                for (int j = 0; j < 8; j++) {
                    int col = wn * 64 + j * 8 + t * 2;
                    *(float2*)&C[(size_t)row0 * 128 + col] =
                        make_float2(acc[i][j][0], acc[i][j][1]);
                    *(float2*)&C[(size_t)(row0 + 8) * 128 + col] =
                        make_float2(acc[i][j][2], acc[i][j][3]);
                    acc[i][j][0] = 0.f; acc[i][j][1] = 0.f;
                    acc[i][j][2] = 0.f; acc[i][j][3] = 0.f;
                }
            }
        }
    }
}

// ---------------- dense (S-layer) attention: bf16 QK^T + tf32 PV (R16 proven) ----
__global__ void __launch_bounds__(256, 1)
dense_attn_tc_kernel(const float* __restrict__ q, const float* __restrict__ k,
                     const float* __restrict__ v, float* __restrict__ o) {
    extern __shared__ float sm[];
    float* Ks = sm;                      // [512][KSTR]
    float* Vs = Ks + 512 * KSTR;         // [512][VSTR]
    float* Ps = Vs + 512 * VSTR;         // [8][64][PSTR]
    const int b = blockIdx.x >> 3, h = blockIdx.x & 7;
    const int base = b * EPG;
    const int tid = threadIdx.x, lane = tid & 31, wid = tid >> 5;
    const int g = lane >> 2, t = lane & 3;
    float* Pw = Ps + wid * 64 * PSTR;

    for (int i = tid; i < 2048; i += 256) {
        int r = i >> 2, c4 = (i & 3) * 4;
        float4 kv = *(const float4*)(k + (size_t)(base + r) * HID + h * DH + c4);
        float4 vv = *(const float4*)(v + (size_t)(base + r) * HID + h * DH + c4);
        Ks[r * KSTR + c4 + 0] = kv.x; Ks[r * KSTR + c4 + 1] = kv.y;
        Ks[r * KSTR + c4 + 2] = kv.z; Ks[r * KSTR + c4 + 3] = kv.w;
        Vs[r * VSTR + c4 + 0] = vv.x; Vs[r * VSTR + c4 + 1] = vv.y;
        Vs[r * VSTR + c4 + 2] = vv.z; Vs[r * VSTR + c4 + 3] = vv.w;
    }

    unsigned qh[4][4], ql[4][4];
    #pragma unroll
    for (int mi = 0; mi < 4; mi++) {
        const size_t r0 = (size_t)(base + wid * 64 + mi * 16 + g) * HID + h * DH;
        const size_t r1 = r0 + (size_t)8 * HID;
        bf16pair(*(const float2*)(q + r0 + 2 * t),     qh[mi][0], ql[mi][0]);
        bf16pair(*(const float2*)(q + r1 + 2 * t),     qh[mi][1], ql[mi][1]);
        bf16pair(*(const float2*)(q + r0 + 2 * t + 8), qh[mi][2], ql[mi][2]);
        bf16pair(*(const float2*)(q + r1 + 2 * t + 8), qh[mi][3], ql[mi][3]);
    }
    __syncthreads();

    float oacc[4][2][4] = {};
    float lrow[8] = {};

    for (int kc = 0; kc < 16; kc++) {
        const int j0 = kc * 32;
        float sacc[4][4][4] = {};
        #pragma unroll
        for (int nj = 0; nj < 4; nj++) {
            const float* kp = Ks + (j0 + nj * 8 + g) * KSTR;
            unsigned bh0, bl0, bh1, bl1;
            bf16pair(*(const float2*)(kp + 2 * t),     bh0, bl0);
            bf16pair(*(const float2*)(kp + 2 * t + 8), bh1, bl1);
            #pragma unroll
            for (int mi = 0; mi < 4; mi++) {
                float* cc = sacc[mi][nj];
                mma_bf16(cc, qh[mi], bl0, bl1);
                mma_bf16(cc, ql[mi], bh0, bh1);
                mma_bf16(cc, qh[mi], bh0, bh1);
            }
        }
        #pragma unroll
        for (int mi = 0; mi < 4; mi++) {
            #pragma unroll
            for (int nj = 0; nj < 4; nj++) {
                float p0 = __uint_as_float(f2tf32u(__expf(sacc[mi][nj][0] * 0.25f)));
                float p1 = __uint_as_float(f2tf32u(__expf(sacc[mi][nj][1] * 0.25f)));
                float p2 = __uint_as_float(f2tf32u(__expf(sacc[mi][nj][2] * 0.25f)));
                float p3 = __uint_as_float(f2tf32u(__expf(sacc[mi][nj][3] * 0.25f)));
                lrow[mi * 2 + 0] += p0 + p1;
                lrow[mi * 2 + 1] += p2 + p3;
                *(float2*)(Pw + (mi * 16 + g) * PSTR + nj * 8 + 2 * t) = make_float2(p0, p1);
                *(float2*)(Pw + (mi * 16 + g + 8) * PSTR + nj * 8 + 2 * t) = make_float2(p2, p3);
            }
        }
        __syncwarp();
        #pragma unroll
        for (int k2 = 0; k2 < 4; k2++) {
            unsigned pa[4][4];
            #pragma unroll
            for (int mi = 0; mi < 4; mi++) {
                const float* p0 = Pw + (mi * 16 + g) * PSTR + k2 * 8 + t;
                const float* p1 = Pw + (mi * 16 + g + 8) * PSTR + k2 * 8 + t;
                pa[mi][0] = __float_as_uint(p0[0]);
                pa[mi][1] = __float_as_uint(p1[0]);
                pa[mi][2] = __float_as_uint(p0[4]);
                pa[mi][3] = __float_as_uint(p1[4]);
            }
            #pragma unroll
            for (int nd = 0; nd < 2; nd++) {
                unsigned vb0 = f2tf32u(Vs[(j0 + k2 * 8 + t) * VSTR + nd * 8 + g]);
                unsigned vb1 = f2tf32u(Vs[(j0 + k2 * 8 + t + 4) * VSTR + nd * 8 + g]);
                #pragma unroll
                for (int mi = 0; mi < 4; mi++)
                    mma_tf32(oacc[mi][nd], pa[mi][0], pa[mi][1], pa[mi][2], pa[mi][3], vb0, vb1);
            }
        }
        __syncwarp();
    }

    #pragma unroll
    for (int i = 0; i < 8; i++) {
        lrow[i] += __shfl_xor_sync(0xFFFFFFFFu, lrow[i], 1);
        lrow[i] += __shfl_xor_sync(0xFFFFFFFFu, lrow[i], 2);
    }
    #pragma unroll
    for (int mi = 0; mi < 4; mi++) {
        float inv0 = 1.f / lrow[mi * 2 + 0];
        float inv1 = 1.f / lrow[mi * 2 + 1];
        size_t r0 = (size_t)(base + wid * 64 + mi * 16 + g) * HID + h * DH;
        size_t r1 = r0 + (size_t)8 * HID;
        #pragma unroll
        for (int nd = 0; nd < 2; nd++) {
            *(float2*)(o + r0 + nd * 8 + 2 * t) =
                make_float2(oacc[mi][nd][0] * inv0, oacc[mi][nd][1] * inv0);
            *(float2*)(o + r1 + nd * 8 + 2 * t) =
                make_float2(oacc[mi][nd][2] * inv1, oacc[mi][nd][3] * inv1);
        }
    }
}

// ---------------- masked multi-head attention (M layers) ----------------
__global__ void attn_kernel(const float* __restrict__ q, const float* __restrict__ k,
                            const float* __restrict__ v, float* __restrict__ o,
                            const unsigned* __restrict__ mask) {
    extern __shared__ float4 sm4[];
    float4* kd = sm4;           // 2048 float4
    float4* vd = sm4 + 2048;
    int b = blockIdx.x >> 3;
    int h = blockIdx.x & 7;
    int base = b * EPG;
    const float* kp = k + (size_t)base * HID + h * DH;
    const float* vp = v + (size_t)base * HID + h * DH;
    for (int i = threadIdx.x; i < 2048; i += 256) {
        int r = i >> 2, c = i & 3;
        kd[i] = *(const float4*)(kp + (size_t)r * HID + c * 4);
        vd[i] = *(const float4*)(vp + (size_t)r * HID + c * 4);
    }
    __syncthreads();

    #pragma unroll
    for (int rr = 0; rr < 2; rr++) {
        int i = threadIdx.x + rr * 256;
        const float* qp = q + (size_t)(base + i) * HID + h * DH;
        float4 q0 = *(const float4*)(qp + 0);
        float4 q1 = *(const float4*)(qp + 4);
        float4 q2 = *(const float4*)(qp + 8);
        float4 q3 = *(const float4*)(qp + 12);

        float l = 0.f;
        float4 a0 = {0,0,0,0}, a1 = {0,0,0,0}, a2 = {0,0,0,0}, a3 = {0,0,0,0};

        const unsigned* mp = mask + (size_t)(base + i) * 16;
        #pragma unroll
        for (int w = 0; w < 16; w++) {
            unsigned bits = mp[w];
            while (bits) {
                int jj = __ffs(bits) - 1;
                bits &= bits - 1;
                int j = (w << 5) + jj;
                const float4 k0 = kd[4*j+0], k1 = kd[4*j+1], k2 = kd[4*j+2], k3 = kd[4*j+3];
                float s = q0.x*k0.x + q0.y*k0.y + q0.z*k0.z + q0.w*k0.w
                        + q1.x*k1.x + q1.y*k1.y + q1.z*k1.z + q1.w*k1.w
                        + q2.x*k2.x + q2.y*k2.y + q2.z*k2.z + q2.w*k2.w
                        + q3.x*k3.x + q3.y*k3.y + q3.z*k3.z + q3.w*k3.w;
                float p = __expf(s * 0.25f);   // 1/sqrt(16)
                l += p;
                const float4 v0 = vd[4*j+0], v1 = vd[4*j+1], v2 = vd[4*j+2], v3 = vd[4*j+3];
                a0.x += p*v0.x; a0.y += p*v0.y; a0.z += p*v0.z; a0.w += p*v0.w;
                a1.x += p*v1.x; a1.y += p*v1.y; a1.z += p*v1.z; a1.w += p*v1.w;
                a2.x += p*v2.x; a2.y += p*v2.y; a2.z += p*v2.z; a2.w += p*v2.w;
                a3.x += p*v3.x; a3.y += p*v3.y; a3.z += p*v3.z; a3.w += p*v3.w;
            }
        }

        float inv = 1.f / l;
        float* op = o + (size_t)(base + i) * HID + h * DH;
        *(float4*)(op + 0)  = make_float4(a0.x*inv, a0.y*inv, a0.z*inv, a0.w*inv);
        *(float4*)(op + 4)  = make_float4(a1.x*inv, a1.y*inv, a1.z*inv, a1.w*inv);
        *(float4*)(op + 8)  = make_float4(a2.x*inv, a2.y*inv, a2.z*inv, a2.w*inv);
        *(float4*)(op + 12) = make_float4(a3.x*inv, a3.y*inv, a3.z*inv, a3.w*inv);
    }
}

// ---------------- fused pool tail: qpool + PMA attn + 3 matvecs + dot ---------
// One block per graph; everything is row-local per graph.
__global__ void pool_tail_kernel(const float* __restrict__ seed, const float* __restrict__ pWq,
                                 const float* __restrict__ k, const float* __restrict__ v,
                                 const float* __restrict__ pWo,
                                 const float* __restrict__ oW1, const float* __restrict__ ob1,
                                 const float* __restrict__ oW2, const float* __restrict__ ob2,
                                 float* __restrict__ out) {
    __shared__ float qp[HID], pooled[HID], t1[HID], t2[HID];
    __shared__ float red[8];
    const int b = blockIdx.x;
    const int tid = threadIdx.x;
    const int w = tid >> 5, lane = tid & 31;

    // qpool = seed @ pWq (redundant per block; trivial)
    if (tid < HID) {
        float s = 0.f;
        for (int kk = 0; kk < HID; kk++) s += seed[kk] * pWq[kk * HID + tid];
        qp[tid] = s;
    }
    __syncthreads();

    // PMA attention: warp w = head w
    float qr[DH];
    #pragma unroll
    for (int d = 0; d < DH; d++) qr[d] = qp[w * DH + d];
    float s[16];
    float mloc = -1e30f;
    #pragma unroll
    for (int tt = 0; tt < 16; tt++) {
        int j = lane + tt * 32;
        const float* kp = k + (size_t)(b * EPG + j) * HID + w * DH;
        float acc = 0.f;
        #pragma unroll
        for (int d = 0; d < DH; d++) acc += qr[d] * kp[d];
        s[tt] = acc * 0.25f;
        mloc = fmaxf(mloc, s[tt]);
    }
    #pragma unroll
    for (int off = 16; off > 0; off >>= 1)
        mloc = fmaxf(mloc, __shfl_xor_sync(0xFFFFFFFFu, mloc, off));
    float l = 0.f;
    float acc[DH];
    #pragma unroll
    for (int d = 0; d < DH; d++) acc[d] = 0.f;
    #pragma unroll
    for (int tt = 0; tt < 16; tt++) {
        int j = lane + tt * 32;
        float p = __expf(s[tt] - mloc);
        l += p;
        const float* vp = v + (size_t)(b * EPG + j) * HID + w * DH;
        #pragma unroll
        for (int d = 0; d < DH; d++) acc[d] += p * vp[d];
    }
    #pragma unroll
    for (int off = 16; off > 0; off >>= 1) {
        l += __shfl_xor_sync(0xFFFFFFFFu, l, off);
        #pragma unroll
        for (int d = 0; d < DH; d++)
            acc[d] += __shfl_xor_sync(0xFFFFFFFFu, acc[d], off);
    }
    if (lane == 0) {
        float inv = 1.f / l;
        #pragma unroll
        for (int d = 0; d < DH; d++) pooled[w * DH + d] = acc[d] * inv;
    }
    __syncthreads();

    // pool2 = pooled @ pWo
    if (tid < HID) {
        float sm2 = 0.f;
        for (int kk = 0; kk < HID; kk++) sm2 += pooled[kk] * pWo[kk * HID + tid];
        t1[tid] = sm2;
    }
    __syncthreads();
    // o1 = relu(pool2 @ oW1 + ob1)
    if (tid < HID) {
        float sm2 = ob1[tid];
        for (int kk = 0; kk < HID; kk++) sm2 += t1[kk] * oW1[kk * HID + tid];
        t2[tid] = fmaxf(sm2, 0.f);
    }
    __syncthreads();
    // out[b] = o1 . oW2 + ob2
    float sd = (tid < HID) ? t2[tid] * oW2[tid] : 0.f;
    #pragma unroll
    for (int off = 16; off > 0; off >>= 1)
        sd += __shfl_xor_sync(0xFFFFFFFFu, sd, off);
    if (lane == 0) red[w] = sd;
    __syncthreads();
    if (tid == 0) {
        float tot = 0.f;
        #pragma unroll
        for (int i = 0; i < 8; i++) tot += red[i];
        out[b] = tot + ob2[0];
    }
}

// ---------------- host launch ----------------
extern "C" void kernel_launch(void* const* d_in, const int* in_sizes, int n_in,
                              void* d_out, int out_size) {
    const float* x       = (const float*)d_in[0];
    const float* ea      = (const float*)d_in[1];
    const float* in_W1   = (const float*)d_in[2];
    const float* in_b1   = (const float*)d_in[3];
    const float* in_W2   = (const float*)d_in[4];
    const float* in_b2   = (const float*)d_in[5];
    const float* Wq      = (const float*)d_in[6];
    const float* Wk      = (const float*)d_in[7];
    const float* Wv      = (const float*)d_in[8];
    const float* Wo      = (const float*)d_in[9];
    const float* ln1_g   = (const float*)d_in[10];
    const float* ln1_b   = (const float*)d_in[11];
    const float* ln2_g   = (const float*)d_in[12];
    const float* ln2_b   = (const float*)d_in[13];
    const float* f_W1    = (const float*)d_in[14];
    const float* f_b1    = (const float*)d_in[15];
    const float* f_W2    = (const float*)d_in[16];
    const float* f_b2    = (const float*)d_in[17];
    const float* seed    = (const float*)d_in[18];
    const float* p_Wq    = (const float*)d_in[19];
    const float* p_Wk    = (const float*)d_in[20];
    const float* p_Wv    = (const float*)d_in[21];
    const float* p_Wo    = (const float*)d_in[22];
    const float* out_W1  = (const float*)d_in[23];
    const float* out_b1  = (const float*)d_in[24];
    const float* out_W2  = (const float*)d_in[25];
    const float* out_b2  = (const float*)d_in[26];
    const int*   ei      = (const int*)d_in[27];

    float *p_h, *p_q, *p_k, *p_v, *p_a, *p_t, *p_feat;
    unsigned *p_wphi, *p_wplo;
    unsigned* p_mask;
    cudaGetSymbolAddress((void**)&p_h, g_h);
    cudaGetSymbolAddress((void**)&p_q, g_q);
    cudaGetSymbolAddress((void**)&p_k, g_k);
    cudaGetSymbolAddress((void**)&p_v, g_v);
    cudaGetSymbolAddress((void**)&p_a, g_a);
    cudaGetSymbolAddress((void**)&p_t, g_t);
    cudaGetSymbolAddress((void**)&p_feat, g_feat);
    cudaGetSymbolAddress((void**)&p_mask, g_mask);
    cudaGetSymbolAddress((void**)&p_wphi, g_wphi);
    cudaGetSymbolAddress((void**)&p_wplo, g_wplo);

    cudaFuncSetAttribute(attn_kernel, cudaFuncAttributeMaxDynamicSharedMemorySize, 65536);
    cudaFuncSetAttribute(gemm_bf16_kernel, cudaFuncAttributeMaxDynamicSharedMemorySize,
                         SMEM_GEMM_BYTES);
    cudaFuncSetAttribute(gemm_multi_kernel, cudaFuncAttributeMaxDynamicSharedMemorySize,
                         SMEM_MULTI);
    cudaFuncSetAttribute(dense_attn_tc_kernel, cudaFuncAttributeMaxDynamicSharedMemorySize,
                         SMEM_DATTN);

    const int gBig = E_TOT / 128;   // 256 blocks

    // weight pre-split + inputs
    split_wp_kernel<<<W_PAIRS / 256, 256>>>(in_W1, in_W2, Wq, Wk, Wv, Wo,
                                            f_W1, f_W2, p_Wk, p_Wv, p_wphi, p_wplo);
    gather_feat_kernel<<<E_TOT, FEAT_DIM>>>(x, ea, ei, p_feat);
    build_mask_kernel<<<B, 256>>>(ei, p_mask);

    #define GEMM1(Ap, OFF, Cp, bias, K, relu) \
        gemm_bf16_kernel<<<gBig, 256, SMEM_GEMM_BYTES>>>(Ap, \
            p_wphi + (OFF), p_wplo + (OFF), Cp, bias, K, relu, \
            nullptr, nullptr, nullptr)

    #define GEMM1_LN(Ap, OFF, bias, lng, lnb, resp) \
        gemm_bf16_kernel<<<gBig, 256, SMEM_GEMM_BYTES>>>(Ap, \
            p_wphi + (OFF), p_wplo + (OFF), nullptr, bias, HID, 0, \
            lng, lnb, resp)

    // input MLP
    GEMM1(p_feat, P_INW1, p_t, in_b1, FEAT_DIM, 1);
    GEMM1(p_t, P_INW2, p_h, in_b2, HID, 0);

    // transformer layers: M, M, S
    for (int L = 0; L < 3; L++) {
        const size_t wo = (size_t)L * LAYER_PSTRIDE;
        gemm_multi_kernel<<<gBig, 256, SMEM_MULTI>>>(p_h,
            p_wphi + P_WQ + wo, p_wphi + P_WK + wo, p_wphi + P_WV + wo,
            p_wplo + P_WQ + wo, p_wplo + P_WK + wo, p_wplo + P_WV + wo,
            p_q, p_k, p_v, 3);
        if (L < 2)
            attn_kernel<<<B * HEADS, 256, 65536>>>(p_q, p_k, p_v, p_a, p_mask);
        else
            dense_attn_tc_kernel<<<B * HEADS, 256, SMEM_DATTN>>>(p_q, p_k, p_v, p_a);
        GEMM1_LN(p_a, P_WO + wo, nullptr, ln1_g + L * HID, ln1_b + L * HID, p_h);
        GEMM1(p_h, P_FW1 + wo, p_t, f_b1 + L * HID, HID, 1);
        GEMM1_LN(p_t, P_FW2 + wo, f_b2 + L * HID, ln2_g + L * HID, ln2_b + L * HID, p_h);
    }

    // PMA pooling: fused K/V projection (NW=2) + fused tail
    gemm_multi_kernel<<<gBig, 256, SMEM_MULTI>>>(p_h,
        p_wphi + P_PWK, p_wphi + P_PWV, p_wphi + P_PWV,
        p_wplo + P_PWK, p_wplo + P_PWV, p_wplo + P_PWV,
        p_k, p_v, p_v, 2);
    pool_tail_kernel<<<B, 256>>>(seed, p_Wq, p_k, p_v, p_Wo,
                                 out_W1, out_b1, out_W2, out_b2, (float*)d_out);
    #undef GEMM1
    #undef GEMM1_LN
}